// round 1
// baseline (speedup 1.0000x reference)
#include <cuda_runtime.h>

#define NPTS 262144
#define NSAMP 8
#define NCH 32
#define NCS 4
#define NPAIR (NPTS * NSAMP)
#define EPSBN 1e-5f

// ---------------- static device scratch (no allocations allowed) ----------------
__device__ float g_q[NPTS * NCH];
__device__ float g_k[NPTS * NCH];
__device__ float g_v[NPTS * NCH];
__device__ float g_w[NPAIR * NCH];   // w pre-BN   (256 MB)
__device__ float g_t[NPAIR * NCS];   // t pre-BN   (32 MB)
// accumulators: [0..2] psum [3..5] psq  [6..37] wsum [38..69] wsq  [70..73] tsum [74..77] tsq
__device__ double g_acc[78];
// coefs (a, c) per BN:  bn(y) = a*y + c
// [0..2] a_p [3..5] c_p  [6..37] a_w [38..69] c_w  [70..73] a_t [74..77] c_t
__device__ float g_coef[78];

// ---------------- K0: zero accumulators ----------------
__global__ void k_zero() {
    int t = threadIdx.x;
    if (t < 78) g_acc[t] = 0.0;
}

// ---------------- K1: q,k,v = x @ W.T + b  (warp handles 4 points, lane=channel) ----
__global__ void k_qkv(const float* __restrict__ x,
                      const float* __restrict__ Wq, const float* __restrict__ bq,
                      const float* __restrict__ Wk, const float* __restrict__ bk,
                      const float* __restrict__ Wv, const float* __restrict__ bv) {
    __shared__ float sWq[1024], sWk[1024], sWv[1024];
    __shared__ float sb[3][32];
    __shared__ float sx[8][4][32];
    int tid = threadIdx.x;
    for (int e = tid; e < 1024; e += blockDim.x) {
        int c = e >> 5, i = e & 31;
        sWq[i * 32 + c] = Wq[e];
        sWk[i * 32 + c] = Wk[e];
        sWv[i * 32 + c] = Wv[e];
    }
    if (tid < 32) { sb[0][tid] = bq[tid]; sb[1][tid] = bk[tid]; sb[2][tid] = bv[tid]; }
    __syncthreads();
    int wid = tid >> 5, lane = tid & 31;
    int n0 = (blockIdx.x * 8 + wid) * 4;
    if (n0 >= NPTS) return;
    float aq[4] = {0, 0, 0, 0}, ak[4] = {0, 0, 0, 0}, av[4] = {0, 0, 0, 0};
#pragma unroll
    for (int pp = 0; pp < 4; pp++) sx[wid][pp][lane] = x[(n0 + pp) * 32 + lane];
    __syncwarp();
#pragma unroll 8
    for (int i = 0; i < 32; i++) {
        float wq = sWq[i * 32 + lane], wk = sWk[i * 32 + lane], wv = sWv[i * 32 + lane];
#pragma unroll
        for (int pp = 0; pp < 4; pp++) {
            float xi = sx[wid][pp][i];
            aq[pp] += xi * wq; ak[pp] += xi * wk; av[pp] += xi * wv;
        }
    }
#pragma unroll
    for (int pp = 0; pp < 4; pp++) {
        g_q[(n0 + pp) * 32 + lane] = aq[pp] + sb[0][lane];
        g_k[(n0 + pp) * 32 + lane] = ak[pp] + sb[1][lane];
        g_v[(n0 + pp) * 32 + lane] = av[pp] + sb[2][lane];
    }
}

// ---------------- K2: stats of y = (p[idx]-p[n]) @ Wp1.T + bp1  (3 channels) ------
__global__ void k_pstats(const float* __restrict__ p, const int* __restrict__ idx,
                         const float* __restrict__ Wp1, const float* __restrict__ bp1) {
    float W[9], b3[3];
#pragma unroll
    for (int i = 0; i < 9; i++) W[i] = Wp1[i];
#pragma unroll
    for (int i = 0; i < 3; i++) b3[i] = bp1[i];
    float s0 = 0, s1 = 0, s2 = 0, q0 = 0, q1 = 0, q2 = 0;
    for (int pr = blockIdx.x * blockDim.x + threadIdx.x; pr < NPAIR;
         pr += gridDim.x * blockDim.x) {
        int n = pr >> 3;
        int j = idx[pr];
        float d0 = p[j * 3 + 0] - p[n * 3 + 0];
        float d1 = p[j * 3 + 1] - p[n * 3 + 1];
        float d2 = p[j * 3 + 2] - p[n * 3 + 2];
        float y0 = W[0] * d0 + W[1] * d1 + W[2] * d2 + b3[0];
        float y1 = W[3] * d0 + W[4] * d1 + W[5] * d2 + b3[1];
        float y2 = W[6] * d0 + W[7] * d1 + W[8] * d2 + b3[2];
        s0 += y0; q0 += y0 * y0;
        s1 += y1; q1 += y1 * y1;
        s2 += y2; q2 += y2 * y2;
    }
#pragma unroll
    for (int o = 16; o; o >>= 1) {
        s0 += __shfl_xor_sync(0xffffffffu, s0, o);
        s1 += __shfl_xor_sync(0xffffffffu, s1, o);
        s2 += __shfl_xor_sync(0xffffffffu, s2, o);
        q0 += __shfl_xor_sync(0xffffffffu, q0, o);
        q1 += __shfl_xor_sync(0xffffffffu, q1, o);
        q2 += __shfl_xor_sync(0xffffffffu, q2, o);
    }
    __shared__ double sh[6];
    if (threadIdx.x < 6) sh[threadIdx.x] = 0.0;
    __syncthreads();
    if ((threadIdx.x & 31) == 0) {
        atomicAdd(&sh[0], (double)s0);
        atomicAdd(&sh[1], (double)s1);
        atomicAdd(&sh[2], (double)s2);
        atomicAdd(&sh[3], (double)q0);
        atomicAdd(&sh[4], (double)q1);
        atomicAdd(&sh[5], (double)q2);
    }
    __syncthreads();
    if (threadIdx.x < 6) atomicAdd(&g_acc[threadIdx.x], sh[threadIdx.x]);
}

// ---------------- finalize BN stats -> affine coefs ----------------
__global__ void k_finalize(const float* __restrict__ g, const float* __restrict__ b,
                           int accOff, int coefOff, int nch) {
    int c = threadIdx.x;
    if (c < nch) {
        double M = (double)NPAIR;
        double m = g_acc[accOff + c] / M;
        double var = g_acc[accOff + nch + c] / M - m * m;
        float rs = rsqrtf((float)var + EPSBN);
        float a = g[c] * rs;
        g_coef[coefOff + c] = a;
        g_coef[coefOff + nch + c] = b[c] - (float)m * a;
    }
}

// ---------------- K4: w = k[idx] - q[n] + p_r ; store + stats  (warp per pair) ----
__global__ void k_w(const float* __restrict__ p, const int* __restrict__ idx,
                    const float* __restrict__ Wp1, const float* __restrict__ bp1,
                    const float* __restrict__ Wp2, const float* __restrict__ bp2) {
    int tid = threadIdx.x, lane = tid & 31, wid = tid >> 5;
    float w20 = Wp2[lane * 3 + 0], w21 = Wp2[lane * 3 + 1], w22 = Wp2[lane * 3 + 2];
    float b2 = bp2[lane];
    float W[9], b3[3], ap[3], cp[3];
#pragma unroll
    for (int i = 0; i < 9; i++) W[i] = Wp1[i];
#pragma unroll
    for (int i = 0; i < 3; i++) { b3[i] = bp1[i]; ap[i] = g_coef[i]; cp[i] = g_coef[3 + i]; }
    float s = 0, ss = 0;
    int gw = blockIdx.x * (blockDim.x >> 5) + wid;
    int nwarps = gridDim.x * (blockDim.x >> 5);
    for (int pr = gw; pr < NPAIR; pr += nwarps) {
        int n = pr >> 3;
        int j = idx[pr];
        float d0 = p[j * 3 + 0] - p[n * 3 + 0];
        float d1 = p[j * 3 + 1] - p[n * 3 + 1];
        float d2 = p[j * 3 + 2] - p[n * 3 + 2];
        float y = W[0] * d0 + W[1] * d1 + W[2] * d2 + b3[0];
        float t0 = fmaxf(0.f, ap[0] * y + cp[0]);
        y = W[3] * d0 + W[4] * d1 + W[5] * d2 + b3[1];
        float t1 = fmaxf(0.f, ap[1] * y + cp[1]);
        y = W[6] * d0 + W[7] * d1 + W[8] * d2 + b3[2];
        float t2 = fmaxf(0.f, ap[2] * y + cp[2]);
        float prc = w20 * t0 + w21 * t1 + w22 * t2 + b2;
        float wv = g_k[j * 32 + lane] - g_q[n * 32 + lane] + prc;
        g_w[(long long)pr * 32 + lane] = wv;
        s += wv; ss += wv * wv;
    }
    __shared__ double shs[32], shq[32];
    if (tid < 32) { shs[tid] = 0.0; shq[tid] = 0.0; }
    __syncthreads();
    atomicAdd(&shs[lane], (double)s);
    atomicAdd(&shq[lane], (double)ss);
    __syncthreads();
    if (tid < 32) {
        atomicAdd(&g_acc[6 + tid], shs[tid]);
        atomicAdd(&g_acc[38 + tid], shq[tid]);
    }
}

// ---------------- K6: t = relu(bn(w)) @ Ww1.T + bww1 ; store + stats --------------
__global__ void k_t(const float* __restrict__ Ww1, const float* __restrict__ bww1) {
    int tid = threadIdx.x, lane = tid & 31, wid = tid >> 5;
    float aw = g_coef[6 + lane], cw = g_coef[38 + lane];
    float w0 = Ww1[lane], w1 = Ww1[32 + lane], w2 = Ww1[64 + lane], w3 = Ww1[96 + lane];
    float bb0 = bww1[0], bb1 = bww1[1], bb2 = bww1[2], bb3 = bww1[3];
    float s0 = 0, s1 = 0, s2 = 0, s3 = 0, q0 = 0, q1 = 0, q2 = 0, q3 = 0;
    int gw = blockIdx.x * (blockDim.x >> 5) + wid;
    int nwarps = gridDim.x * (blockDim.x >> 5);
    for (int pr = gw; pr < NPAIR; pr += nwarps) {
        float val = fmaxf(0.f, aw * g_w[(long long)pr * 32 + lane] + cw);
        float p0 = val * w0, p1 = val * w1, p2 = val * w2, p3 = val * w3;
#pragma unroll
        for (int o = 16; o; o >>= 1) {
            p0 += __shfl_xor_sync(0xffffffffu, p0, o);
            p1 += __shfl_xor_sync(0xffffffffu, p1, o);
            p2 += __shfl_xor_sync(0xffffffffu, p2, o);
            p3 += __shfl_xor_sync(0xffffffffu, p3, o);
        }
        p0 += bb0; p1 += bb1; p2 += bb2; p3 += bb3;
        if (lane == 0) {
            float4 t4; t4.x = p0; t4.y = p1; t4.z = p2; t4.w = p3;
            *(float4*)&g_t[pr * 4] = t4;
            s0 += p0; q0 += p0 * p0;
            s1 += p1; q1 += p1 * p1;
            s2 += p2; q2 += p2 * p2;
            s3 += p3; q3 += p3 * p3;
        }
    }
    __shared__ double sh[8];
    if (tid < 8) sh[tid] = 0.0;
    __syncthreads();
    if (lane == 0) {
        atomicAdd(&sh[0], (double)s0);
        atomicAdd(&sh[1], (double)s1);
        atomicAdd(&sh[2], (double)s2);
        atomicAdd(&sh[3], (double)s3);
        atomicAdd(&sh[4], (double)q0);
        atomicAdd(&sh[5], (double)q1);
        atomicAdd(&sh[6], (double)q2);
        atomicAdd(&sh[7], (double)q3);
    }
    __syncthreads();
    if (tid < 8) atomicAdd(&g_acc[70 + tid], sh[tid]);
}

// ---------------- K8: softmax over ns + weighted sum -> out  (warp per point) -----
__global__ void k_out(const float* __restrict__ p, const int* __restrict__ idx,
                      const float* __restrict__ Wp1, const float* __restrict__ bp1,
                      const float* __restrict__ Wp2, const float* __restrict__ bp2,
                      const float* __restrict__ Ww2, const float* __restrict__ bww2,
                      float* __restrict__ out) {
    int tid = threadIdx.x, lane = tid & 31, wid = tid >> 5;
    int cc = lane & 3;
    float at0 = g_coef[70], at1 = g_coef[71], at2 = g_coef[72], at3 = g_coef[73];
    float ct0 = g_coef[74], ct1 = g_coef[75], ct2 = g_coef[76], ct3 = g_coef[77];
    float v20 = Ww2[cc * 4 + 0], v21 = Ww2[cc * 4 + 1], v22 = Ww2[cc * 4 + 2], v23 = Ww2[cc * 4 + 3];
    float bcc = bww2[cc];
    float w20 = Wp2[lane * 3 + 0], w21 = Wp2[lane * 3 + 1], w22 = Wp2[lane * 3 + 2];
    float b2 = bp2[lane];
    float W[9], b3[3], ap[3], cp[3];
#pragma unroll
    for (int i = 0; i < 9; i++) W[i] = Wp1[i];
#pragma unroll
    for (int i = 0; i < 3; i++) { b3[i] = bp1[i]; ap[i] = g_coef[i]; cp[i] = g_coef[3 + i]; }
    int gw = blockIdx.x * (blockDim.x >> 5) + wid;
    int nwarps = gridDim.x * (blockDim.x >> 5);
    for (int n = gw; n < NPTS; n += nwarps) {
        float logit[8], aval[8];
        float pn0 = p[n * 3 + 0], pn1 = p[n * 3 + 1], pn2 = p[n * 3 + 2];
#pragma unroll
        for (int ns = 0; ns < 8; ns++) {
            int prI = n * 8 + ns;
            int j = idx[prI];
            float4 t4 = *(const float4*)&g_t[prI * 4];
            float u0 = fmaxf(0.f, at0 * t4.x + ct0);
            float u1 = fmaxf(0.f, at1 * t4.y + ct1);
            float u2 = fmaxf(0.f, at2 * t4.z + ct2);
            float u3 = fmaxf(0.f, at3 * t4.w + ct3);
            logit[ns] = v20 * u0 + v21 * u1 + v22 * u2 + v23 * u3 + bcc;
            float d0 = p[j * 3 + 0] - pn0;
            float d1 = p[j * 3 + 1] - pn1;
            float d2 = p[j * 3 + 2] - pn2;
            float y = W[0] * d0 + W[1] * d1 + W[2] * d2 + b3[0];
            float t0 = fmaxf(0.f, ap[0] * y + cp[0]);
            y = W[3] * d0 + W[4] * d1 + W[5] * d2 + b3[1];
            float t1 = fmaxf(0.f, ap[1] * y + cp[1]);
            y = W[6] * d0 + W[7] * d1 + W[8] * d2 + b3[2];
            float t2 = fmaxf(0.f, ap[2] * y + cp[2]);
            float prc = w20 * t0 + w21 * t1 + w22 * t2 + b2;
            aval[ns] = g_v[j * 32 + lane] + prc;
        }
        float m = logit[0];
#pragma unroll
        for (int ns = 1; ns < 8; ns++) m = fmaxf(m, logit[ns]);
        float se = 0.f;
#pragma unroll
        for (int ns = 0; ns < 8; ns++) { float e = __expf(logit[ns] - m); logit[ns] = e; se += e; }
        float inv = 1.f / se;
        float o = 0.f;
#pragma unroll
        for (int ns = 0; ns < 8; ns++) o += aval[ns] * logit[ns];
        out[n * 32 + lane] = o * inv;
    }
}

// ---------------- launch ----------------
extern "C" void kernel_launch(void* const* d_in, const int* in_sizes, int n_in,
                              void* d_out, int out_size) {
    const float* p   = (const float*)d_in[0];
    const float* x   = (const float*)d_in[1];
    const int*   idx = (const int*)d_in[2];
    const float* Wq  = (const float*)d_in[3];  const float* bq   = (const float*)d_in[4];
    const float* Wk  = (const float*)d_in[5];  const float* bk   = (const float*)d_in[6];
    const float* Wv  = (const float*)d_in[7];  const float* bv   = (const float*)d_in[8];
    const float* Wp1 = (const float*)d_in[9];  const float* bp1  = (const float*)d_in[10];
    const float* gp  = (const float*)d_in[11]; const float* bp   = (const float*)d_in[12];
    const float* Wp2 = (const float*)d_in[13]; const float* bp2  = (const float*)d_in[14];
    const float* gw1 = (const float*)d_in[15]; const float* bw1  = (const float*)d_in[16];
    const float* Ww1 = (const float*)d_in[17]; const float* bww1 = (const float*)d_in[18];
    const float* gw2 = (const float*)d_in[19]; const float* bw2  = (const float*)d_in[20];
    const float* Ww2 = (const float*)d_in[21]; const float* bww2 = (const float*)d_in[22];
    float* out = (float*)d_out;

    k_zero<<<1, 128>>>();
    k_qkv<<<NPTS / 32, 256>>>(x, Wq, bq, Wk, bk, Wv, bv);
    k_pstats<<<2048, 256>>>(p, idx, Wp1, bp1);
    k_finalize<<<1, 32>>>(gp, bp, 0, 0, 3);
    k_w<<<4096, 256>>>(p, idx, Wp1, bp1, Wp2, bp2);
    k_finalize<<<1, 32>>>(gw1, bw1, 6, 6, 32);
    k_t<<<4096, 256>>>(Ww1, bww1);
    k_finalize<<<1, 32>>>(gw2, bw2, 70, 70, 4);
    k_out<<<4096, 256>>>(p, idx, Wp1, bp1, Wp2, bp2, Ww2, bww2, out);
}

// round 2
// speedup vs baseline: 1.4126x; 1.4126x over previous
#include <cuda_runtime.h>

#define NPTS 262144
#define NSAMP 8
#define NCH 32
#define NCS 4
#define NPAIR (NPTS * NSAMP)
#define EPSBN 1e-5f

// ---------------- static device scratch ----------------
__device__ float g_q[NPTS * NCH];
__device__ float g_k[NPTS * NCH];
__device__ float g_v[NPTS * NCH];
__device__ float g_t[NPAIR * NCS];   // t pre-BN (32 MB)
// accumulators: [0..2] psum [3..5] psq  [6..37] wsum [38..69] wsq  [70..73] tsum [74..77] tsq
__device__ double g_acc[78];

// ---------------- K1: q,k,v = x @ W.T + b ; block 0 zeroes accumulators ----------
__global__ void k_qkv(const float* __restrict__ x,
                      const float* __restrict__ Wq, const float* __restrict__ bq,
                      const float* __restrict__ Wk, const float* __restrict__ bk,
                      const float* __restrict__ Wv, const float* __restrict__ bv) {
    __shared__ float sWq[1024], sWk[1024], sWv[1024];
    __shared__ float sb[3][32];
    __shared__ float sx[8][4][32];
    int tid = threadIdx.x;
    if (blockIdx.x == 0 && tid < 78) g_acc[tid] = 0.0;
    for (int e = tid; e < 1024; e += blockDim.x) {
        int c = e >> 5, i = e & 31;
        sWq[i * 32 + c] = Wq[e];
        sWk[i * 32 + c] = Wk[e];
        sWv[i * 32 + c] = Wv[e];
    }
    if (tid < 32) { sb[0][tid] = bq[tid]; sb[1][tid] = bk[tid]; sb[2][tid] = bv[tid]; }
    __syncthreads();
    int wid = tid >> 5, lane = tid & 31;
    int n0 = (blockIdx.x * 8 + wid) * 4;
    if (n0 >= NPTS) return;
    float aq[4] = {0, 0, 0, 0}, ak[4] = {0, 0, 0, 0}, av[4] = {0, 0, 0, 0};
#pragma unroll
    for (int pp = 0; pp < 4; pp++) sx[wid][pp][lane] = x[(n0 + pp) * 32 + lane];
    __syncwarp();
#pragma unroll 8
    for (int i = 0; i < 32; i++) {
        float wq = sWq[i * 32 + lane], wk = sWk[i * 32 + lane], wv = sWv[i * 32 + lane];
#pragma unroll
        for (int pp = 0; pp < 4; pp++) {
            float xi = sx[wid][pp][i];
            aq[pp] += xi * wq; ak[pp] += xi * wk; av[pp] += xi * wv;
        }
    }
#pragma unroll
    for (int pp = 0; pp < 4; pp++) {
        g_q[(n0 + pp) * 32 + lane] = aq[pp] + sb[0][lane];
        g_k[(n0 + pp) * 32 + lane] = ak[pp] + sb[1][lane];
        g_v[(n0 + pp) * 32 + lane] = av[pp] + sb[2][lane];
    }
}

// ---------------- K2: stats of y = (p[idx]-p[n]) @ Wp1.T + bp1 --------------------
__global__ void k_pstats(const float* __restrict__ p, const int* __restrict__ idx,
                         const float* __restrict__ Wp1, const float* __restrict__ bp1) {
    float W[9], b3[3];
#pragma unroll
    for (int i = 0; i < 9; i++) W[i] = Wp1[i];
#pragma unroll
    for (int i = 0; i < 3; i++) b3[i] = bp1[i];
    float s0 = 0, s1 = 0, s2 = 0, q0 = 0, q1 = 0, q2 = 0;
    for (int pr = blockIdx.x * blockDim.x + threadIdx.x; pr < NPAIR;
         pr += gridDim.x * blockDim.x) {
        int n = pr >> 3;
        int j = idx[pr];
        float d0 = p[j * 3 + 0] - p[n * 3 + 0];
        float d1 = p[j * 3 + 1] - p[n * 3 + 1];
        float d2 = p[j * 3 + 2] - p[n * 3 + 2];
        float y0 = W[0] * d0 + W[1] * d1 + W[2] * d2 + b3[0];
        float y1 = W[3] * d0 + W[4] * d1 + W[5] * d2 + b3[1];
        float y2 = W[6] * d0 + W[7] * d1 + W[8] * d2 + b3[2];
        s0 += y0; q0 += y0 * y0;
        s1 += y1; q1 += y1 * y1;
        s2 += y2; q2 += y2 * y2;
    }
#pragma unroll
    for (int o = 16; o; o >>= 1) {
        s0 += __shfl_xor_sync(0xffffffffu, s0, o);
        s1 += __shfl_xor_sync(0xffffffffu, s1, o);
        s2 += __shfl_xor_sync(0xffffffffu, s2, o);
        q0 += __shfl_xor_sync(0xffffffffu, q0, o);
        q1 += __shfl_xor_sync(0xffffffffu, q1, o);
        q2 += __shfl_xor_sync(0xffffffffu, q2, o);
    }
    __shared__ double sh[6];
    if (threadIdx.x < 6) sh[threadIdx.x] = 0.0;
    __syncthreads();
    if ((threadIdx.x & 31) == 0) {
        atomicAdd(&sh[0], (double)s0);
        atomicAdd(&sh[1], (double)s1);
        atomicAdd(&sh[2], (double)s2);
        atomicAdd(&sh[3], (double)q0);
        atomicAdd(&sh[4], (double)q1);
        atomicAdd(&sh[5], (double)q2);
    }
    __syncthreads();
    if (threadIdx.x < 6) atomicAdd(&g_acc[threadIdx.x], sh[threadIdx.x]);
}

// ---------------- K3: stats of w = k[idx] - q[n] + p_r  (no store; warp/point) ----
__global__ void k_wstats(const float* __restrict__ p, const int* __restrict__ idx,
                         const float* __restrict__ Wp1, const float* __restrict__ bp1,
                         const float* __restrict__ gp, const float* __restrict__ bpv,
                         const float* __restrict__ Wp2, const float* __restrict__ bp2) {
    __shared__ float s_ap[3], s_cp[3];
    __shared__ double shs[32], shq[32];
    int tid = threadIdx.x, lane = tid & 31, wid = tid >> 5;
    if (tid < 3) {
        double M = (double)NPAIR;
        double m = g_acc[tid] / M;
        double var = g_acc[3 + tid] / M - m * m;
        float a = gp[tid] * rsqrtf((float)var + EPSBN);
        s_ap[tid] = a; s_cp[tid] = bpv[tid] - (float)m * a;
    }
    if (tid < 32) { shs[tid] = 0.0; shq[tid] = 0.0; }
    __syncthreads();
    float W[9], b3[3];
#pragma unroll
    for (int i = 0; i < 9; i++) W[i] = Wp1[i];
#pragma unroll
    for (int i = 0; i < 3; i++) b3[i] = bp1[i];
    float ap0 = s_ap[0], ap1 = s_ap[1], ap2 = s_ap[2];
    float cp0 = s_cp[0], cp1 = s_cp[1], cp2 = s_cp[2];
    float w20 = Wp2[lane * 3 + 0], w21 = Wp2[lane * 3 + 1], w22 = Wp2[lane * 3 + 2];
    float b2 = bp2[lane];
    float s = 0.f, ss = 0.f;
    int gw = blockIdx.x * 8 + wid, nw = gridDim.x * 8;
    for (int n = gw; n < NPTS; n += nw) {
        float pn0 = p[n * 3 + 0], pn1 = p[n * 3 + 1], pn2 = p[n * 3 + 2];
        float qv = g_q[n * 32 + lane];
#pragma unroll
        for (int ns = 0; ns < 8; ns++) {
            int j = idx[n * 8 + ns];
            float d0 = p[j * 3 + 0] - pn0;
            float d1 = p[j * 3 + 1] - pn1;
            float d2 = p[j * 3 + 2] - pn2;
            float y = W[0] * d0 + W[1] * d1 + W[2] * d2 + b3[0];
            float t0 = fmaxf(0.f, ap0 * y + cp0);
            y = W[3] * d0 + W[4] * d1 + W[5] * d2 + b3[1];
            float t1 = fmaxf(0.f, ap1 * y + cp1);
            y = W[6] * d0 + W[7] * d1 + W[8] * d2 + b3[2];
            float t2 = fmaxf(0.f, ap2 * y + cp2);
            float prc = w20 * t0 + w21 * t1 + w22 * t2 + b2;
            float wv = g_k[j * 32 + lane] - qv + prc;
            s += wv; ss += wv * wv;
        }
    }
    atomicAdd(&shs[lane], (double)s);
    atomicAdd(&shq[lane], (double)ss);
    __syncthreads();
    if (tid < 32) {
        atomicAdd(&g_acc[6 + tid], shs[tid]);
        atomicAdd(&g_acc[38 + tid], shq[tid]);
    }
}

// ---------------- K4: t = relu(bn(w)) @ Ww1.T + bww1 ; recompute w; warp/point ----
__global__ void k_t(const float* __restrict__ p, const int* __restrict__ idx,
                    const float* __restrict__ Wp1, const float* __restrict__ bp1,
                    const float* __restrict__ Wp2, const float* __restrict__ bp2,
                    const float* __restrict__ gp, const float* __restrict__ bpv,
                    const float* __restrict__ gw1, const float* __restrict__ bw1,
                    const float* __restrict__ Ww1, const float* __restrict__ bww1) {
    __shared__ float s_ap[3], s_cp[3], s_aw[32], s_cw[32];
    __shared__ float sw[8][8][33];
    __shared__ double sh[8];
    int tid = threadIdx.x, lane = tid & 31, wid = tid >> 5;
    if (tid < 3) {
        double M = (double)NPAIR;
        double m = g_acc[tid] / M;
        double var = g_acc[3 + tid] / M - m * m;
        float a = gp[tid] * rsqrtf((float)var + EPSBN);
        s_ap[tid] = a; s_cp[tid] = bpv[tid] - (float)m * a;
    }
    if (tid < 32) {
        double M = (double)NPAIR;
        double m = g_acc[6 + tid] / M;
        double var = g_acc[38 + tid] / M - m * m;
        float a = gw1[tid] * rsqrtf((float)var + EPSBN);
        s_aw[tid] = a; s_cw[tid] = bw1[tid] - (float)m * a;
    }
    if (tid < 8) sh[tid] = 0.0;
    __syncthreads();
    float W[9], b3[3];
#pragma unroll
    for (int i = 0; i < 9; i++) W[i] = Wp1[i];
#pragma unroll
    for (int i = 0; i < 3; i++) b3[i] = bp1[i];
    float ap0 = s_ap[0], ap1 = s_ap[1], ap2 = s_ap[2];
    float cp0 = s_cp[0], cp1 = s_cp[1], cp2 = s_cp[2];
    float aw = s_aw[lane], cw = s_cw[lane];
    float w20 = Wp2[lane * 3 + 0], w21 = Wp2[lane * 3 + 1], w22 = Wp2[lane * 3 + 2];
    float b2 = bp2[lane];
    int m4 = lane & 3, pl = lane >> 2;
    float wrow[32];
#pragma unroll
    for (int c2 = 0; c2 < 32; c2++) wrow[c2] = Ww1[m4 * 32 + c2];
    float bm = bww1[m4];
    float sm = 0.f, qm = 0.f;
    int gw = blockIdx.x * 8 + wid, nw = gridDim.x * 8;
    for (int n = gw; n < NPTS; n += nw) {
        float pn0 = p[n * 3 + 0], pn1 = p[n * 3 + 1], pn2 = p[n * 3 + 2];
        float qv = g_q[n * 32 + lane];
#pragma unroll
        for (int ns = 0; ns < 8; ns++) {
            int j = idx[n * 8 + ns];
            float d0 = p[j * 3 + 0] - pn0;
            float d1 = p[j * 3 + 1] - pn1;
            float d2 = p[j * 3 + 2] - pn2;
            float y = W[0] * d0 + W[1] * d1 + W[2] * d2 + b3[0];
            float t0 = fmaxf(0.f, ap0 * y + cp0);
            y = W[3] * d0 + W[4] * d1 + W[5] * d2 + b3[1];
            float t1 = fmaxf(0.f, ap1 * y + cp1);
            y = W[6] * d0 + W[7] * d1 + W[8] * d2 + b3[2];
            float t2 = fmaxf(0.f, ap2 * y + cp2);
            float prc = w20 * t0 + w21 * t1 + w22 * t2 + b2;
            float wv = g_k[j * 32 + lane] - qv + prc;
            sw[wid][ns][lane] = fmaxf(0.f, aw * wv + cw);
        }
        __syncwarp();
        float tval = bm;
#pragma unroll
        for (int c2 = 0; c2 < 32; c2++) tval += sw[wid][pl][c2] * wrow[c2];
        g_t[n * 32 + lane] = tval;      // == g_t[(n*8+pl)*4 + m4], coalesced 128B
        sm += tval; qm += tval * tval;
        __syncwarp();
    }
    // reduce lanes sharing m4 (stride-4 groups): xor offsets 4, 8, 16
#pragma unroll
    for (int o = 4; o < 32; o <<= 1) {
        sm += __shfl_xor_sync(0xffffffffu, sm, o);
        qm += __shfl_xor_sync(0xffffffffu, qm, o);
    }
    if (lane < 4) {
        atomicAdd(&sh[lane], (double)sm);
        atomicAdd(&sh[4 + lane], (double)qm);
    }
    __syncthreads();
    if (tid < 8) atomicAdd(&g_acc[70 + tid], sh[tid]);
}

// ---------------- K5: softmax over ns + weighted sum -> out  (warp per point) -----
__global__ void k_out(const float* __restrict__ p, const int* __restrict__ idx,
                      const float* __restrict__ Wp1, const float* __restrict__ bp1,
                      const float* __restrict__ Wp2, const float* __restrict__ bp2,
                      const float* __restrict__ gp, const float* __restrict__ bpv,
                      const float* __restrict__ gw2, const float* __restrict__ bw2,
                      const float* __restrict__ Ww2, const float* __restrict__ bww2,
                      float* __restrict__ out) {
    __shared__ float s_ap[3], s_cp[3], s_at[4], s_ct[4];
    int tid = threadIdx.x, lane = tid & 31, wid = tid >> 5;
    if (tid < 3) {
        double M = (double)NPAIR;
        double m = g_acc[tid] / M;
        double var = g_acc[3 + tid] / M - m * m;
        float a = gp[tid] * rsqrtf((float)var + EPSBN);
        s_ap[tid] = a; s_cp[tid] = bpv[tid] - (float)m * a;
    }
    if (tid < 4) {
        double M = (double)NPAIR;
        double m = g_acc[70 + tid] / M;
        double var = g_acc[74 + tid] / M - m * m;
        float a = gw2[tid] * rsqrtf((float)var + EPSBN);
        s_at[tid] = a; s_ct[tid] = bw2[tid] - (float)m * a;
    }
    __syncthreads();
    int cc = lane & 3;
    float at0 = s_at[0], at1 = s_at[1], at2 = s_at[2], at3 = s_at[3];
    float ct0 = s_ct[0], ct1 = s_ct[1], ct2 = s_ct[2], ct3 = s_ct[3];
    float v20 = Ww2[cc * 4 + 0], v21 = Ww2[cc * 4 + 1], v22 = Ww2[cc * 4 + 2], v23 = Ww2[cc * 4 + 3];
    float bcc = bww2[cc];
    float w20 = Wp2[lane * 3 + 0], w21 = Wp2[lane * 3 + 1], w22 = Wp2[lane * 3 + 2];
    float b2 = bp2[lane];
    float W[9], b3[3];
#pragma unroll
    for (int i = 0; i < 9; i++) W[i] = Wp1[i];
#pragma unroll
    for (int i = 0; i < 3; i++) b3[i] = bp1[i];
    float ap0 = s_ap[0], ap1 = s_ap[1], ap2 = s_ap[2];
    float cp0 = s_cp[0], cp1 = s_cp[1], cp2 = s_cp[2];
    int gw = blockIdx.x * 8 + wid, nw = gridDim.x * 8;
    for (int n = gw; n < NPTS; n += nw) {
        float logit[8], aval[8];
        float pn0 = p[n * 3 + 0], pn1 = p[n * 3 + 1], pn2 = p[n * 3 + 2];
#pragma unroll
        for (int ns = 0; ns < 8; ns++) {
            int prI = n * 8 + ns;
            int j = idx[prI];
            float4 t4 = *(const float4*)&g_t[prI * 4];
            float u0 = fmaxf(0.f, at0 * t4.x + ct0);
            float u1 = fmaxf(0.f, at1 * t4.y + ct1);
            float u2 = fmaxf(0.f, at2 * t4.z + ct2);
            float u3 = fmaxf(0.f, at3 * t4.w + ct3);
            logit[ns] = v20 * u0 + v21 * u1 + v22 * u2 + v23 * u3 + bcc;
            float d0 = p[j * 3 + 0] - pn0;
            float d1 = p[j * 3 + 1] - pn1;
            float d2 = p[j * 3 + 2] - pn2;
            float y = W[0] * d0 + W[1] * d1 + W[2] * d2 + b3[0];
            float t0 = fmaxf(0.f, ap0 * y + cp0);
            y = W[3] * d0 + W[4] * d1 + W[5] * d2 + b3[1];
            float t1 = fmaxf(0.f, ap1 * y + cp1);
            y = W[6] * d0 + W[7] * d1 + W[8] * d2 + b3[2];
            float t2 = fmaxf(0.f, ap2 * y + cp2);
            float prc = w20 * t0 + w21 * t1 + w22 * t2 + b2;
            aval[ns] = g_v[j * 32 + lane] + prc;
        }
        float m = logit[0];
#pragma unroll
        for (int ns = 1; ns < 8; ns++) m = fmaxf(m, logit[ns]);
        float se = 0.f;
#pragma unroll
        for (int ns = 0; ns < 8; ns++) { float e = __expf(logit[ns] - m); logit[ns] = e; se += e; }
        float inv = 1.f / se;
        float o = 0.f;
#pragma unroll
        for (int ns = 0; ns < 8; ns++) o += aval[ns] * logit[ns];
        out[n * 32 + lane] = o * inv;
    }
}

// ---------------- launch ----------------
extern "C" void kernel_launch(void* const* d_in, const int* in_sizes, int n_in,
                              void* d_out, int out_size) {
    const float* p   = (const float*)d_in[0];
    const float* x   = (const float*)d_in[1];
    const int*   idx = (const int*)d_in[2];
    const float* Wq  = (const float*)d_in[3];  const float* bq   = (const float*)d_in[4];
    const float* Wk  = (const float*)d_in[5];  const float* bk   = (const float*)d_in[6];
    const float* Wv  = (const float*)d_in[7];  const float* bv   = (const float*)d_in[8];
    const float* Wp1 = (const float*)d_in[9];  const float* bp1  = (const float*)d_in[10];
    const float* gp  = (const float*)d_in[11]; const float* bp   = (const float*)d_in[12];
    const float* Wp2 = (const float*)d_in[13]; const float* bp2  = (const float*)d_in[14];
    const float* gw1 = (const float*)d_in[15]; const float* bw1  = (const float*)d_in[16];
    const float* Ww1 = (const float*)d_in[17]; const float* bww1 = (const float*)d_in[18];
    const float* gw2 = (const float*)d_in[19]; const float* bw2  = (const float*)d_in[20];
    const float* Ww2 = (const float*)d_in[21]; const float* bww2 = (const float*)d_in[22];
    float* out = (float*)d_out;

    k_qkv<<<NPTS / 32, 256>>>(x, Wq, bq, Wk, bk, Wv, bv);
    k_pstats<<<2048, 256>>>(p, idx, Wp1, bp1);
    k_wstats<<<2048, 256>>>(p, idx, Wp1, bp1, gp, bp, Wp2, bp2);
    k_t<<<2048, 256>>>(p, idx, Wp1, bp1, Wp2, bp2, gp, bp, gw1, bw1, Ww1, bww1);
    k_out<<<4096, 256>>>(p, idx, Wp1, bp1, Wp2, bp2, gp, bp, gw2, bw2, Ww2, bww2, out);
}

// round 3
// speedup vs baseline: 2.0086x; 1.4219x over previous
#include <cuda_runtime.h>

#define NPTS 262144
#define NSAMP 8
#define NPAIR (NPTS * NSAMP)
#define EPSBN 1e-5f
#define FULLM 0xffffffffu

// ---------------- static device scratch ----------------
__device__ float g_q[NPTS * 32];
__device__ float g_k[NPTS * 32];
__device__ float g_v[NPTS * 32];
__device__ float g_t3[NPAIR * 3];   // relu(bn_p(p_r @ Wp1.T + bp1)) per pair (24 MB)
__device__ float g_t[NPAIR * 4];    // t pre-BN (32 MB)
// [0..2] psum [3..5] psq  [6..37] wsum [38..69] wsq  [70..73] tsum [74..77] tsq
__device__ double g_acc[78];

// ---------------- K0: zero accumulators ----------------
__global__ void k_zero() {
    int t = threadIdx.x;
    if (t < 78) g_acc[t] = 0.0;
}

// ---------------- K1: fused qkv (blocks 0..8191) + pstats (blocks 8192..10239) ----
__global__ void __launch_bounds__(256) k_fused1(
        const float* __restrict__ p, const float* __restrict__ x,
        const int* __restrict__ idx,
        const float* __restrict__ Wq, const float* __restrict__ bq,
        const float* __restrict__ Wk, const float* __restrict__ bk,
        const float* __restrict__ Wv, const float* __restrict__ bv,
        const float* __restrict__ Wp1, const float* __restrict__ bp1) {
    int tid = threadIdx.x;
    if (blockIdx.x < NPTS / 32) {
        // ---- qkv: warp handles 4 points, lane = channel ----
        __shared__ float sWq[1024], sWk[1024], sWv[1024];
        __shared__ float sb[3][32];
        __shared__ float sx[8][4][32];
        for (int e = tid; e < 1024; e += 256) {
            int c = e >> 5, i = e & 31;
            sWq[i * 32 + c] = Wq[e];
            sWk[i * 32 + c] = Wk[e];
            sWv[i * 32 + c] = Wv[e];
        }
        if (tid < 32) { sb[0][tid] = bq[tid]; sb[1][tid] = bk[tid]; sb[2][tid] = bv[tid]; }
        __syncthreads();
        int wid = tid >> 5, lane = tid & 31;
        int n0 = (blockIdx.x * 8 + wid) * 4;
        float aq[4] = {0, 0, 0, 0}, ak[4] = {0, 0, 0, 0}, av[4] = {0, 0, 0, 0};
#pragma unroll
        for (int pp = 0; pp < 4; pp++) sx[wid][pp][lane] = x[(n0 + pp) * 32 + lane];
        __syncwarp();
#pragma unroll 8
        for (int i = 0; i < 32; i++) {
            float wq = sWq[i * 32 + lane], wk = sWk[i * 32 + lane], wv = sWv[i * 32 + lane];
#pragma unroll
            for (int pp = 0; pp < 4; pp++) {
                float xi = sx[wid][pp][i];
                aq[pp] += xi * wq; ak[pp] += xi * wk; av[pp] += xi * wv;
            }
        }
#pragma unroll
        for (int pp = 0; pp < 4; pp++) {
            g_q[(n0 + pp) * 32 + lane] = aq[pp] + sb[0][lane];
            g_k[(n0 + pp) * 32 + lane] = ak[pp] + sb[1][lane];
            g_v[(n0 + pp) * 32 + lane] = av[pp] + sb[2][lane];
        }
    } else {
        // ---- pstats: grid-stride over pairs ----
        float W[9], b3[3];
#pragma unroll
        for (int i = 0; i < 9; i++) W[i] = Wp1[i];
#pragma unroll
        for (int i = 0; i < 3; i++) b3[i] = bp1[i];
        float s0 = 0, s1 = 0, s2 = 0, q0 = 0, q1 = 0, q2 = 0;
        int bid = blockIdx.x - NPTS / 32;
        for (int pr = bid * 256 + tid; pr < NPAIR; pr += 2048 * 256) {
            int n = pr >> 3;
            int j = idx[pr];
            float d0 = p[j * 3 + 0] - p[n * 3 + 0];
            float d1 = p[j * 3 + 1] - p[n * 3 + 1];
            float d2 = p[j * 3 + 2] - p[n * 3 + 2];
            float y0 = W[0] * d0 + W[1] * d1 + W[2] * d2 + b3[0];
            float y1 = W[3] * d0 + W[4] * d1 + W[5] * d2 + b3[1];
            float y2 = W[6] * d0 + W[7] * d1 + W[8] * d2 + b3[2];
            s0 += y0; q0 += y0 * y0;
            s1 += y1; q1 += y1 * y1;
            s2 += y2; q2 += y2 * y2;
        }
#pragma unroll
        for (int o = 16; o; o >>= 1) {
            s0 += __shfl_xor_sync(FULLM, s0, o);
            s1 += __shfl_xor_sync(FULLM, s1, o);
            s2 += __shfl_xor_sync(FULLM, s2, o);
            q0 += __shfl_xor_sync(FULLM, q0, o);
            q1 += __shfl_xor_sync(FULLM, q1, o);
            q2 += __shfl_xor_sync(FULLM, q2, o);
        }
        __shared__ double sh[6];
        if (tid < 6) sh[tid] = 0.0;
        __syncthreads();
        if ((tid & 31) == 0) {
            atomicAdd(&sh[0], (double)s0);
            atomicAdd(&sh[1], (double)s1);
            atomicAdd(&sh[2], (double)s2);
            atomicAdd(&sh[3], (double)q0);
            atomicAdd(&sh[4], (double)q1);
            atomicAdd(&sh[5], (double)q2);
        }
        __syncthreads();
        if (tid < 6) atomicAdd(&g_acc[tid], sh[tid]);
    }
}

// ---------------- K2: t3 = relu(bn_p((p[j]-p[n]) @ Wp1.T + bp1)), once per pair ---
__global__ void __launch_bounds__(256, 4) k_t3(
        const float* __restrict__ p, const int* __restrict__ idx,
        const float* __restrict__ gp, const float* __restrict__ bpv,
        const float* __restrict__ Wp1, const float* __restrict__ bp1) {
    __shared__ float s_ap[3], s_cp[3];
    if (threadIdx.x < 3) {
        double M = (double)NPAIR;
        double m = g_acc[threadIdx.x] / M;
        double var = g_acc[3 + threadIdx.x] / M - m * m;
        float a = gp[threadIdx.x] * rsqrtf((float)var + EPSBN);
        s_ap[threadIdx.x] = a; s_cp[threadIdx.x] = bpv[threadIdx.x] - (float)m * a;
    }
    __syncthreads();
    float W[9], b3[3];
#pragma unroll
    for (int i = 0; i < 9; i++) W[i] = Wp1[i];
#pragma unroll
    for (int i = 0; i < 3; i++) b3[i] = bp1[i];
    float ap0 = s_ap[0], ap1 = s_ap[1], ap2 = s_ap[2];
    float cp0 = s_cp[0], cp1 = s_cp[1], cp2 = s_cp[2];
    for (int pr = blockIdx.x * 256 + threadIdx.x; pr < NPAIR; pr += gridDim.x * 256) {
        int n = pr >> 3;
        int j = idx[pr];
        float d0 = p[j * 3 + 0] - p[n * 3 + 0];
        float d1 = p[j * 3 + 1] - p[n * 3 + 1];
        float d2 = p[j * 3 + 2] - p[n * 3 + 2];
        float y = W[0] * d0 + W[1] * d1 + W[2] * d2 + b3[0];
        float t0 = fmaxf(0.f, ap0 * y + cp0);
        y = W[3] * d0 + W[4] * d1 + W[5] * d2 + b3[1];
        float t1 = fmaxf(0.f, ap1 * y + cp1);
        y = W[6] * d0 + W[7] * d1 + W[8] * d2 + b3[2];
        float t2 = fmaxf(0.f, ap2 * y + cp2);
        g_t3[pr * 3 + 0] = t0;
        g_t3[pr * 3 + 1] = t1;
        g_t3[pr * 3 + 2] = t2;
    }
}

// ---------------- K3: stats of w = k[idx] - q[n] + prc  (warp per point) ----------
__global__ void __launch_bounds__(256, 4) k_wstats(
        const int* __restrict__ idx,
        const float* __restrict__ Wp2, const float* __restrict__ bp2) {
    __shared__ double shs[32], shq[32];
    int tid = threadIdx.x, lane = tid & 31, wid = tid >> 5;
    if (tid < 32) { shs[tid] = 0.0; shq[tid] = 0.0; }
    __syncthreads();
    float w20 = Wp2[lane * 3 + 0], w21 = Wp2[lane * 3 + 1], w22 = Wp2[lane * 3 + 2];
    float b2 = bp2[lane];
    float s = 0.f, ss = 0.f;
    int gw = blockIdx.x * 8 + wid, nw = gridDim.x * 8;
    for (int n = gw; n < NPTS; n += nw) {
        int jv = (lane < 8) ? idx[n * 8 + lane] : 0;
        float t3v = (lane < 24) ? g_t3[n * 24 + lane] : 0.f;
        float qv = g_q[n * 32 + lane];
#pragma unroll
        for (int ns = 0; ns < 8; ns++) {
            int j = __shfl_sync(FULLM, jv, ns);
            float t0 = __shfl_sync(FULLM, t3v, ns * 3 + 0);
            float t1 = __shfl_sync(FULLM, t3v, ns * 3 + 1);
            float t2 = __shfl_sync(FULLM, t3v, ns * 3 + 2);
            float prc = w20 * t0 + w21 * t1 + w22 * t2 + b2;
            float wv = g_k[j * 32 + lane] - qv + prc;
            s += wv; ss += wv * wv;
        }
    }
    atomicAdd(&shs[lane], (double)s);
    atomicAdd(&shq[lane], (double)ss);
    __syncthreads();
    if (tid < 32) {
        atomicAdd(&g_acc[6 + tid], shs[tid]);
        atomicAdd(&g_acc[38 + tid], shq[tid]);
    }
}

// ---------------- K4: t = relu(bn_w(w)) @ Ww1.T + bww1 ; warp per point ----------
__global__ void __launch_bounds__(256, 4) k_t(
        const int* __restrict__ idx,
        const float* __restrict__ Wp2, const float* __restrict__ bp2,
        const float* __restrict__ gw1, const float* __restrict__ bw1,
        const float* __restrict__ Ww1, const float* __restrict__ bww1) {
    __shared__ float s_aw[32], s_cw[32];
    __shared__ __align__(16) float sw[8][8][36];
    __shared__ __align__(16) float sWw1[4 * 36];
    __shared__ double sh[8];
    int tid = threadIdx.x, lane = tid & 31, wid = tid >> 5;
    if (tid < 32) {
        double M = (double)NPAIR;
        double m = g_acc[6 + tid] / M;
        double var = g_acc[38 + tid] / M - m * m;
        float a = gw1[tid] * rsqrtf((float)var + EPSBN);
        s_aw[tid] = a; s_cw[tid] = bw1[tid] - (float)m * a;
    }
    if (tid < 128) sWw1[(tid >> 5) * 36 + (tid & 31)] = Ww1[tid];
    if (tid < 8) sh[tid] = 0.0;
    __syncthreads();
    float aw = s_aw[lane], cw = s_cw[lane];
    float w20 = Wp2[lane * 3 + 0], w21 = Wp2[lane * 3 + 1], w22 = Wp2[lane * 3 + 2];
    float b2 = bp2[lane];
    int m4 = lane & 3, pl = lane >> 2;
    float bm = bww1[m4];
    const float4* wr4 = (const float4*)&sWw1[m4 * 36];
    float sm = 0.f, qm = 0.f;
    int gw = blockIdx.x * 8 + wid, nw = gridDim.x * 8;
    for (int n = gw; n < NPTS; n += nw) {
        int jv = (lane < 8) ? idx[n * 8 + lane] : 0;
        float t3v = (lane < 24) ? g_t3[n * 24 + lane] : 0.f;
        float qv = g_q[n * 32 + lane];
#pragma unroll
        for (int ns = 0; ns < 8; ns++) {
            int j = __shfl_sync(FULLM, jv, ns);
            float t0 = __shfl_sync(FULLM, t3v, ns * 3 + 0);
            float t1 = __shfl_sync(FULLM, t3v, ns * 3 + 1);
            float t2 = __shfl_sync(FULLM, t3v, ns * 3 + 2);
            float prc = w20 * t0 + w21 * t1 + w22 * t2 + b2;
            float wv = g_k[j * 32 + lane] - qv + prc;
            sw[wid][ns][lane] = fmaxf(0.f, aw * wv + cw);
        }
        __syncwarp();
        const float4* a4p = (const float4*)&sw[wid][pl][0];
        float tval = bm;
#pragma unroll
        for (int c4 = 0; c4 < 8; c4++) {
            float4 a4 = a4p[c4], b4 = wr4[c4];
            tval += a4.x * b4.x + a4.y * b4.y + a4.z * b4.z + a4.w * b4.w;
        }
        g_t[n * 32 + lane] = tval;   // == g_t[(n*8+pl)*4 + m4], coalesced
        sm += tval; qm += tval * tval;
        __syncwarp();
    }
#pragma unroll
    for (int o = 4; o < 32; o <<= 1) {
        sm += __shfl_xor_sync(FULLM, sm, o);
        qm += __shfl_xor_sync(FULLM, qm, o);
    }
    if (lane < 4) {
        atomicAdd(&sh[lane], (double)sm);
        atomicAdd(&sh[4 + lane], (double)qm);
    }
    __syncthreads();
    if (tid < 8) atomicAdd(&g_acc[70 + tid], sh[tid]);
}

// ---------------- K5: softmax + weighted sum -> out  (warp per point) ------------
__global__ void __launch_bounds__(256, 4) k_out(
        const int* __restrict__ idx,
        const float* __restrict__ Wp2, const float* __restrict__ bp2,
        const float* __restrict__ gw2, const float* __restrict__ bw2,
        const float* __restrict__ Ww2, const float* __restrict__ bww2,
        float* __restrict__ out) {
    __shared__ float s_at[4], s_ct[4];
    int tid = threadIdx.x, lane = tid & 31, wid = tid >> 5;
    if (tid < 4) {
        double M = (double)NPAIR;
        double m = g_acc[70 + tid] / M;
        double var = g_acc[74 + tid] / M - m * m;
        float a = gw2[tid] * rsqrtf((float)var + EPSBN);
        s_at[tid] = a; s_ct[tid] = bw2[tid] - (float)m * a;
    }
    __syncthreads();
    int cc = lane & 3;
    float at0 = s_at[0], at1 = s_at[1], at2 = s_at[2], at3 = s_at[3];
    float ct0 = s_ct[0], ct1 = s_ct[1], ct2 = s_ct[2], ct3 = s_ct[3];
    float v20 = Ww2[cc * 4 + 0], v21 = Ww2[cc * 4 + 1];
    float v22 = Ww2[cc * 4 + 2], v23 = Ww2[cc * 4 + 3];
    float bcc = bww2[cc];
    float w20 = Wp2[lane * 3 + 0], w21 = Wp2[lane * 3 + 1], w22 = Wp2[lane * 3 + 2];
    float b2 = bp2[lane];
    int gw = blockIdx.x * 8 + wid, nw = gridDim.x * 8;
    for (int n = gw; n < NPTS; n += nw) {
        int jv = (lane < 8) ? idx[n * 8 + lane] : 0;
        float t3v = (lane < 24) ? g_t3[n * 24 + lane] : 0.f;
        float logit[8], aval[8];
#pragma unroll
        for (int ns = 0; ns < 8; ns++) {
            int j = __shfl_sync(FULLM, jv, ns);
            float4 t4 = *(const float4*)&g_t[(n * 8 + ns) * 4];
            float u0 = fmaxf(0.f, at0 * t4.x + ct0);
            float u1 = fmaxf(0.f, at1 * t4.y + ct1);
            float u2 = fmaxf(0.f, at2 * t4.z + ct2);
            float u3 = fmaxf(0.f, at3 * t4.w + ct3);
            logit[ns] = v20 * u0 + v21 * u1 + v22 * u2 + v23 * u3 + bcc;
            float t0 = __shfl_sync(FULLM, t3v, ns * 3 + 0);
            float t1 = __shfl_sync(FULLM, t3v, ns * 3 + 1);
            float t2 = __shfl_sync(FULLM, t3v, ns * 3 + 2);
            float prc = w20 * t0 + w21 * t1 + w22 * t2 + b2;
            aval[ns] = g_v[j * 32 + lane] + prc;
        }
        float m = logit[0];
#pragma unroll
        for (int ns = 1; ns < 8; ns++) m = fmaxf(m, logit[ns]);
        float se = 0.f;
#pragma unroll
        for (int ns = 0; ns < 8; ns++) { float e = __expf(logit[ns] - m); logit[ns] = e; se += e; }
        float inv = 1.f / se;
        float o = 0.f;
#pragma unroll
        for (int ns = 0; ns < 8; ns++) o += aval[ns] * logit[ns];
        out[n * 32 + lane] = o * inv;
    }
}

// ---------------- launch ----------------
extern "C" void kernel_launch(void* const* d_in, const int* in_sizes, int n_in,
                              void* d_out, int out_size) {
    const float* p   = (const float*)d_in[0];
    const float* x   = (const float*)d_in[1];
    const int*   idx = (const int*)d_in[2];
    const float* Wq  = (const float*)d_in[3];  const float* bq   = (const float*)d_in[4];
    const float* Wk  = (const float*)d_in[5];  const float* bk   = (const float*)d_in[6];
    const float* Wv  = (const float*)d_in[7];  const float* bv   = (const float*)d_in[8];
    const float* Wp1 = (const float*)d_in[9];  const float* bp1  = (const float*)d_in[10];
    const float* gp  = (const float*)d_in[11]; const float* bp   = (const float*)d_in[12];
    const float* Wp2 = (const float*)d_in[13]; const float* bp2  = (const float*)d_in[14];
    const float* gw1 = (const float*)d_in[15]; const float* bw1  = (const float*)d_in[16];
    const float* Ww1 = (const float*)d_in[17]; const float* bww1 = (const float*)d_in[18];
    const float* gw2 = (const float*)d_in[19]; const float* bw2  = (const float*)d_in[20];
    const float* Ww2 = (const float*)d_in[21]; const float* bww2 = (const float*)d_in[22];
    float* out = (float*)d_out;

    k_zero<<<1, 128>>>();
    k_fused1<<<NPTS / 32 + 2048, 256>>>(p, x, idx, Wq, bq, Wk, bk, Wv, bv, Wp1, bp1);
    k_t3<<<2048, 256>>>(p, idx, gp, bp, Wp1, bp1);
    k_wstats<<<2048, 256>>>(idx, Wp2, bp2);
    k_t<<<2048, 256>>>(idx, Wp2, bp2, gw1, bw1, Ww1, bww1);
    k_out<<<4096, 256>>>(idx, Wp2, bp2, gw2, bw2, Ww2, bww2, out);
}

// round 4
// speedup vs baseline: 2.5680x; 1.2785x over previous
#include <cuda_runtime.h>

#define NPTS 262144
#define NSAMP 8
#define NPAIR (NPTS * NSAMP)
#define EPSBN 1e-5f
#define FULLM 0xffffffffu
#define QKVB 1024

// ---------------- static device scratch ----------------
__device__ float g_q[NPTS * 32];
__device__ float g_k[NPTS * 32];
__device__ float g_v[NPTS * 32];
__device__ float g_t3[NPAIR * 3];   // relu(bn_p(p_r @ Wp1.T + bp1)) per pair (24 MB)
__device__ float g_t[NPAIR * 4];    // t pre-BN (32 MB)
// [0..2] psum [3..5] psq  [6..37] wsum [38..69] wsq  [70..73] tsum [74..77] tsq
__device__ double g_acc[78];

// ---------------- K0: zero accumulators ----------------
__global__ void k_zero() {
    int t = threadIdx.x;
    if (t < 78) g_acc[t] = 0.0;
}

// ---------------- K1: fused qkv (blocks 0..QKVB-1, grid-stride) + pstats ----------
__global__ void __launch_bounds__(256) k_fused1(
        const float* __restrict__ p, const float* __restrict__ x,
        const int* __restrict__ idx,
        const float* __restrict__ Wq, const float* __restrict__ bq,
        const float* __restrict__ Wk, const float* __restrict__ bk,
        const float* __restrict__ Wv, const float* __restrict__ bv,
        const float* __restrict__ Wp1, const float* __restrict__ bp1) {
    int tid = threadIdx.x;
    if (blockIdx.x < QKVB) {
        // ---- qkv: warp handles 4 points per chunk; block strides over chunks ----
        __shared__ float sWq[1024], sWk[1024], sWv[1024];
        __shared__ float sb[3][32];
        __shared__ float sx[8][4][32];
        for (int e = tid; e < 1024; e += 256) {
            int c = e >> 5, i = e & 31;
            sWq[i * 32 + c] = Wq[e];
            sWk[i * 32 + c] = Wk[e];
            sWv[i * 32 + c] = Wv[e];
        }
        if (tid < 32) { sb[0][tid] = bq[tid]; sb[1][tid] = bk[tid]; sb[2][tid] = bv[tid]; }
        __syncthreads();
        int wid = tid >> 5, lane = tid & 31;
        float bqv = sb[0][lane], bkv = sb[1][lane], bvv = sb[2][lane];
        for (int blk = blockIdx.x; blk < NPTS / 32; blk += QKVB) {
            int n0 = (blk * 8 + wid) * 4;
            float aq[4] = {0, 0, 0, 0}, ak[4] = {0, 0, 0, 0}, av[4] = {0, 0, 0, 0};
#pragma unroll
            for (int pp = 0; pp < 4; pp++) sx[wid][pp][lane] = x[(n0 + pp) * 32 + lane];
            __syncwarp();
#pragma unroll 8
            for (int i = 0; i < 32; i++) {
                float wq = sWq[i * 32 + lane], wk = sWk[i * 32 + lane], wv = sWv[i * 32 + lane];
#pragma unroll
                for (int pp = 0; pp < 4; pp++) {
                    float xi = sx[wid][pp][i];
                    aq[pp] += xi * wq; ak[pp] += xi * wk; av[pp] += xi * wv;
                }
            }
#pragma unroll
            for (int pp = 0; pp < 4; pp++) {
                g_q[(n0 + pp) * 32 + lane] = aq[pp] + bqv;
                g_k[(n0 + pp) * 32 + lane] = ak[pp] + bkv;
                g_v[(n0 + pp) * 32 + lane] = av[pp] + bvv;
            }
            __syncwarp();
        }
    } else {
        // ---- pstats: grid-stride over pairs ----
        float W[9], b3[3];
#pragma unroll
        for (int i = 0; i < 9; i++) W[i] = Wp1[i];
#pragma unroll
        for (int i = 0; i < 3; i++) b3[i] = bp1[i];
        float s0 = 0, s1 = 0, s2 = 0, q0 = 0, q1 = 0, q2 = 0;
        int bid = blockIdx.x - QKVB;
        for (int pr = bid * 256 + tid; pr < NPAIR; pr += 2048 * 256) {
            int n = pr >> 3;
            int j = idx[pr];
            float d0 = p[j * 3 + 0] - p[n * 3 + 0];
            float d1 = p[j * 3 + 1] - p[n * 3 + 1];
            float d2 = p[j * 3 + 2] - p[n * 3 + 2];
            float y0 = W[0] * d0 + W[1] * d1 + W[2] * d2 + b3[0];
            float y1 = W[3] * d0 + W[4] * d1 + W[5] * d2 + b3[1];
            float y2 = W[6] * d0 + W[7] * d1 + W[8] * d2 + b3[2];
            s0 += y0; q0 += y0 * y0;
            s1 += y1; q1 += y1 * y1;
            s2 += y2; q2 += y2 * y2;
        }
#pragma unroll
        for (int o = 16; o; o >>= 1) {
            s0 += __shfl_xor_sync(FULLM, s0, o);
            s1 += __shfl_xor_sync(FULLM, s1, o);
            s2 += __shfl_xor_sync(FULLM, s2, o);
            q0 += __shfl_xor_sync(FULLM, q0, o);
            q1 += __shfl_xor_sync(FULLM, q1, o);
            q2 += __shfl_xor_sync(FULLM, q2, o);
        }
        __shared__ double sh[6];
        if (tid < 6) sh[tid] = 0.0;
        __syncthreads();
        if ((tid & 31) == 0) {
            atomicAdd(&sh[0], (double)s0);
            atomicAdd(&sh[1], (double)s1);
            atomicAdd(&sh[2], (double)s2);
            atomicAdd(&sh[3], (double)q0);
            atomicAdd(&sh[4], (double)q1);
            atomicAdd(&sh[5], (double)q2);
        }
        __syncthreads();
        if (tid < 6) atomicAdd(&g_acc[tid], sh[tid]);
    }
}

// ---------------- K2: fused t3-gen + wstats  (warp per point) ---------------------
__global__ void __launch_bounds__(256, 5) k_wt3(
        const float* __restrict__ p, const int* __restrict__ idx,
        const float* __restrict__ gp, const float* __restrict__ bpv,
        const float* __restrict__ Wp1, const float* __restrict__ bp1,
        const float* __restrict__ Wp2, const float* __restrict__ bp2) {
    __shared__ float s_ap[3], s_cp[3];
    __shared__ double shs[32], shq[32];
    int tid = threadIdx.x, lane = tid & 31, wid = tid >> 5;
    if (tid < 3) {
        double M = (double)NPAIR;
        double m = g_acc[tid] / M;
        double var = g_acc[3 + tid] / M - m * m;
        float a = gp[tid] * rsqrtf((float)var + EPSBN);
        s_ap[tid] = a; s_cp[tid] = bpv[tid] - (float)m * a;
    }
    if (tid < 32) { shs[tid] = 0.0; shq[tid] = 0.0; }
    __syncthreads();
    // per-lane t3-gen constants: lane<24 maps to (pair, comp)
    int pr_i = (lane < 24) ? lane : 23;
    int pair = pr_i / 3, comp = pr_i - pair * 3;
    float wc0 = Wp1[comp * 3 + 0], wc1 = Wp1[comp * 3 + 1], wc2 = Wp1[comp * 3 + 2];
    float b3c = bp1[comp];
    float apc = s_ap[comp], cpc = s_cp[comp];
    // per-lane wstats constants
    float w20 = Wp2[lane * 3 + 0], w21 = Wp2[lane * 3 + 1], w22 = Wp2[lane * 3 + 2];
    float b2 = bp2[lane];
    float s = 0.f, ss = 0.f;
    int gw = blockIdx.x * 8 + wid, nw = gridDim.x * 8;
    for (int n = gw; n < NPTS; n += nw) {
        int jv = (lane < 8) ? idx[n * 8 + lane] : 0;
        int jme = __shfl_sync(FULLM, jv, pair);
        float pd = p[jme * 3 + comp] - p[n * 3 + comp];
        float d0 = __shfl_sync(FULLM, pd, pair * 3 + 0);
        float d1 = __shfl_sync(FULLM, pd, pair * 3 + 1);
        float d2 = __shfl_sync(FULLM, pd, pair * 3 + 2);
        float y = wc0 * d0 + wc1 * d1 + wc2 * d2 + b3c;
        float t3v = fmaxf(0.f, apc * y + cpc);
        if (lane < 24) g_t3[n * 24 + lane] = t3v;
        float qv = g_q[n * 32 + lane];
#pragma unroll
        for (int ns = 0; ns < 8; ns++) {
            int j = __shfl_sync(FULLM, jv, ns);
            float t0 = __shfl_sync(FULLM, t3v, ns * 3 + 0);
            float t1 = __shfl_sync(FULLM, t3v, ns * 3 + 1);
            float t2 = __shfl_sync(FULLM, t3v, ns * 3 + 2);
            float prc = w20 * t0 + w21 * t1 + w22 * t2 + b2;
            float wv = g_k[j * 32 + lane] - qv + prc;
            s += wv; ss += wv * wv;
        }
    }
    atomicAdd(&shs[lane], (double)s);
    atomicAdd(&shq[lane], (double)ss);
    __syncthreads();
    if (tid < 32) {
        atomicAdd(&g_acc[6 + tid], shs[tid]);
        atomicAdd(&g_acc[38 + tid], shq[tid]);
    }
}

// ---------------- K3: t = relu(bn_w(w)) @ Ww1.T + bww1 ; warp per point ----------
__global__ void __launch_bounds__(256, 5) k_t(
        const int* __restrict__ idx,
        const float* __restrict__ Wp2, const float* __restrict__ bp2,
        const float* __restrict__ gw1, const float* __restrict__ bw1,
        const float* __restrict__ Ww1, const float* __restrict__ bww1) {
    __shared__ float s_aw[32], s_cw[32];
    __shared__ __align__(16) float sw[8][8][36];
    __shared__ __align__(16) float sWw1[4 * 36];
    __shared__ double sh[8];
    int tid = threadIdx.x, lane = tid & 31, wid = tid >> 5;
    if (tid < 32) {
        double M = (double)NPAIR;
        double m = g_acc[6 + tid] / M;
        double var = g_acc[38 + tid] / M - m * m;
        float a = gw1[tid] * rsqrtf((float)var + EPSBN);
        s_aw[tid] = a; s_cw[tid] = bw1[tid] - (float)m * a;
    }
    if (tid < 128) sWw1[(tid >> 5) * 36 + (tid & 31)] = Ww1[tid];
    if (tid < 8) sh[tid] = 0.0;
    __syncthreads();
    float aw = s_aw[lane], cw = s_cw[lane];
    float w20 = Wp2[lane * 3 + 0], w21 = Wp2[lane * 3 + 1], w22 = Wp2[lane * 3 + 2];
    float b2 = bp2[lane];
    int m4 = lane & 3, pl = lane >> 2;
    float bm = bww1[m4];
    const float4* wr4 = (const float4*)&sWw1[m4 * 36];
    float sm = 0.f, qm = 0.f;
    int gw = blockIdx.x * 8 + wid, nw = gridDim.x * 8;
    for (int n = gw; n < NPTS; n += nw) {
        int jv = (lane < 8) ? idx[n * 8 + lane] : 0;
        float t3v = (lane < 24) ? g_t3[n * 24 + lane] : 0.f;
        float qv = g_q[n * 32 + lane];
#pragma unroll
        for (int ns = 0; ns < 8; ns++) {
            int j = __shfl_sync(FULLM, jv, ns);
            float t0 = __shfl_sync(FULLM, t3v, ns * 3 + 0);
            float t1 = __shfl_sync(FULLM, t3v, ns * 3 + 1);
            float t2 = __shfl_sync(FULLM, t3v, ns * 3 + 2);
            float prc = w20 * t0 + w21 * t1 + w22 * t2 + b2;
            float wv = g_k[j * 32 + lane] - qv + prc;
            sw[wid][ns][lane] = fmaxf(0.f, aw * wv + cw);
        }
        __syncwarp();
        const float4* a4p = (const float4*)&sw[wid][pl][0];
        float tval = bm;
#pragma unroll
        for (int c4 = 0; c4 < 8; c4++) {
            float4 a4 = a4p[c4], b4 = wr4[c4];
            tval += a4.x * b4.x + a4.y * b4.y + a4.z * b4.z + a4.w * b4.w;
        }
        g_t[n * 32 + lane] = tval;   // == g_t[(n*8+pl)*4 + m4], coalesced
        sm += tval; qm += tval * tval;
        __syncwarp();
    }
#pragma unroll
    for (int o = 4; o < 32; o <<= 1) {
        sm += __shfl_xor_sync(FULLM, sm, o);
        qm += __shfl_xor_sync(FULLM, qm, o);
    }
    if (lane < 4) {
        atomicAdd(&sh[lane], (double)sm);
        atomicAdd(&sh[4 + lane], (double)qm);
    }
    __syncthreads();
    if (tid < 8) atomicAdd(&g_acc[70 + tid], sh[tid]);
}

// ---------------- K4: softmax + weighted sum -> out  (warp per point) ------------
__global__ void __launch_bounds__(256, 5) k_out(
        const int* __restrict__ idx,
        const float* __restrict__ Wp2, const float* __restrict__ bp2,
        const float* __restrict__ gw2, const float* __restrict__ bw2,
        const float* __restrict__ Ww2, const float* __restrict__ bww2,
        float* __restrict__ out) {
    __shared__ float s_at[4], s_ct[4];
    int tid = threadIdx.x, lane = tid & 31, wid = tid >> 5;
    if (tid < 4) {
        double M = (double)NPAIR;
        double m = g_acc[70 + tid] / M;
        double var = g_acc[74 + tid] / M - m * m;
        float a = gw2[tid] * rsqrtf((float)var + EPSBN);
        s_at[tid] = a; s_ct[tid] = bw2[tid] - (float)m * a;
    }
    __syncthreads();
    int cc = lane & 3;
    float at0 = s_at[0], at1 = s_at[1], at2 = s_at[2], at3 = s_at[3];
    float ct0 = s_ct[0], ct1 = s_ct[1], ct2 = s_ct[2], ct3 = s_ct[3];
    float v20 = Ww2[cc * 4 + 0], v21 = Ww2[cc * 4 + 1];
    float v22 = Ww2[cc * 4 + 2], v23 = Ww2[cc * 4 + 3];
    float bcc = bww2[cc];
    float w20 = Wp2[lane * 3 + 0], w21 = Wp2[lane * 3 + 1], w22 = Wp2[lane * 3 + 2];
    float b2 = bp2[lane];
    int gw = blockIdx.x * 8 + wid, nw = gridDim.x * 8;
    for (int n = gw; n < NPTS; n += nw) {
        int jv = (lane < 8) ? idx[n * 8 + lane] : 0;
        float t3v = (lane < 24) ? g_t3[n * 24 + lane] : 0.f;
        float logit[8];
#pragma unroll
        for (int ns = 0; ns < 8; ns++) {
            float4 t4 = *(const float4*)&g_t[(n * 8 + ns) * 4];
            float u0 = fmaxf(0.f, at0 * t4.x + ct0);
            float u1 = fmaxf(0.f, at1 * t4.y + ct1);
            float u2 = fmaxf(0.f, at2 * t4.z + ct2);
            float u3 = fmaxf(0.f, at3 * t4.w + ct3);
            logit[ns] = v20 * u0 + v21 * u1 + v22 * u2 + v23 * u3 + bcc;
        }
        float m = logit[0];
#pragma unroll
        for (int ns = 1; ns < 8; ns++) m = fmaxf(m, logit[ns]);
        float se = 0.f;
#pragma unroll
        for (int ns = 0; ns < 8; ns++) { float e = __expf(logit[ns] - m); logit[ns] = e; se += e; }
        float inv = 1.f / se;
        float o = 0.f;
#pragma unroll
        for (int ns = 0; ns < 8; ns++) {
            int j = __shfl_sync(FULLM, jv, ns);
            float t0 = __shfl_sync(FULLM, t3v, ns * 3 + 0);
            float t1 = __shfl_sync(FULLM, t3v, ns * 3 + 1);
            float t2 = __shfl_sync(FULLM, t3v, ns * 3 + 2);
            float prc = w20 * t0 + w21 * t1 + w22 * t2 + b2;
            o += (g_v[j * 32 + lane] + prc) * logit[ns];
        }
        out[n * 32 + lane] = o * inv;
    }
}

// ---------------- launch ----------------
extern "C" void kernel_launch(void* const* d_in, const int* in_sizes, int n_in,
                              void* d_out, int out_size) {
    const float* p   = (const float*)d_in[0];
    const float* x   = (const float*)d_in[1];
    const int*   idx = (const int*)d_in[2];
    const float* Wq  = (const float*)d_in[3];  const float* bq   = (const float*)d_in[4];
    const float* Wk  = (const float*)d_in[5];  const float* bk   = (const float*)d_in[6];
    const float* Wv  = (const float*)d_in[7];  const float* bv   = (const float*)d_in[8];
    const float* Wp1 = (const float*)d_in[9];  const float* bp1  = (const float*)d_in[10];
    const float* gp  = (const float*)d_in[11]; const float* bp   = (const float*)d_in[12];
    const float* Wp2 = (const float*)d_in[13]; const float* bp2  = (const float*)d_in[14];
    const float* gw1 = (const float*)d_in[15]; const float* bw1  = (const float*)d_in[16];
    const float* Ww1 = (const float*)d_in[17]; const float* bww1 = (const float*)d_in[18];
    const float* gw2 = (const float*)d_in[19]; const float* bw2  = (const float*)d_in[20];
    const float* Ww2 = (const float*)d_in[21]; const float* bww2 = (const float*)d_in[22];
    float* out = (float*)d_out;

    k_zero<<<1, 128>>>();
    k_fused1<<<QKVB + 2048, 256>>>(p, x, idx, Wq, bq, Wk, bk, Wv, bv, Wp1, bp1);
    k_wt3<<<740, 256>>>(p, idx, gp, bp, Wp1, bp1, Wp2, bp2);
    k_t<<<740, 256>>>(idx, Wp2, bp2, gw1, bw1, Ww1, bww1);
    k_out<<<740, 256>>>(idx, Wp2, bp2, gw2, bw2, Ww2, bww2, out);
}

// round 5
// speedup vs baseline: 3.0315x; 1.1805x over previous
#include <cuda_runtime.h>

#define NPTS 262144
#define NSAMP 8
#define NPAIR (NPTS * NSAMP)
#define HALF_N (NPTS / 2)
#define EPSBN 1e-5f
#define FULLM 0xffffffffu
#define QKVB 1024
#define GATHER_GRID 592   // 4 blocks/SM * 148 SMs

// ---------------- static device scratch ----------------
__device__ float g_q[NPTS * 32];
__device__ float g_k[NPTS * 32];
__device__ float g_v[NPTS * 32];
__device__ float g_t3[NPAIR * 3];   // relu(bn_p(p_r @ Wp1.T + bp1)) per pair (24 MB)
__device__ float g_t[NPAIR * 4];    // t pre-BN (32 MB)
// [0..2] psum [3..5] psq  [6..37] wsum [38..69] wsq  [70..73] tsum [74..77] tsq
__device__ double g_acc[78];

// ---------------- K0: zero accumulators ----------------
__global__ void k_zero() {
    int t = threadIdx.x;
    if (t < 78) g_acc[t] = 0.0;
}

// ---------------- K1: fused qkv (blocks 0..QKVB-1, grid-stride) + pstats ----------
__global__ void __launch_bounds__(256) k_fused1(
        const float* __restrict__ p, const float* __restrict__ x,
        const int* __restrict__ idx,
        const float* __restrict__ Wq, const float* __restrict__ bq,
        const float* __restrict__ Wk, const float* __restrict__ bk,
        const float* __restrict__ Wv, const float* __restrict__ bv,
        const float* __restrict__ Wp1, const float* __restrict__ bp1) {
    int tid = threadIdx.x;
    if (blockIdx.x < QKVB) {
        __shared__ float sWq[1024], sWk[1024], sWv[1024];
        __shared__ float sb[3][32];
        __shared__ float sx[8][4][32];
        for (int e = tid; e < 1024; e += 256) {
            int c = e >> 5, i = e & 31;
            sWq[i * 32 + c] = Wq[e];
            sWk[i * 32 + c] = Wk[e];
            sWv[i * 32 + c] = Wv[e];
        }
        if (tid < 32) { sb[0][tid] = bq[tid]; sb[1][tid] = bk[tid]; sb[2][tid] = bv[tid]; }
        __syncthreads();
        int wid = tid >> 5, lane = tid & 31;
        float bqv = sb[0][lane], bkv = sb[1][lane], bvv = sb[2][lane];
        for (int blk = blockIdx.x; blk < NPTS / 32; blk += QKVB) {
            int n0 = (blk * 8 + wid) * 4;
            float aq[4] = {0, 0, 0, 0}, ak[4] = {0, 0, 0, 0}, av[4] = {0, 0, 0, 0};
#pragma unroll
            for (int pp = 0; pp < 4; pp++) sx[wid][pp][lane] = x[(n0 + pp) * 32 + lane];
            __syncwarp();
#pragma unroll 8
            for (int i = 0; i < 32; i++) {
                float wq = sWq[i * 32 + lane], wk = sWk[i * 32 + lane], wv = sWv[i * 32 + lane];
#pragma unroll
                for (int pp = 0; pp < 4; pp++) {
                    float xi = sx[wid][pp][i];
                    aq[pp] += xi * wq; ak[pp] += xi * wk; av[pp] += xi * wv;
                }
            }
#pragma unroll
            for (int pp = 0; pp < 4; pp++) {
                g_q[(n0 + pp) * 32 + lane] = aq[pp] + bqv;
                g_k[(n0 + pp) * 32 + lane] = ak[pp] + bkv;
                g_v[(n0 + pp) * 32 + lane] = av[pp] + bvv;
            }
            __syncwarp();
        }
    } else {
        float W[9], b3[3];
#pragma unroll
        for (int i = 0; i < 9; i++) W[i] = Wp1[i];
#pragma unroll
        for (int i = 0; i < 3; i++) b3[i] = bp1[i];
        float s0 = 0, s1 = 0, s2 = 0, q0 = 0, q1 = 0, q2 = 0;
        int bid = blockIdx.x - QKVB;
        for (int pr = bid * 256 + tid; pr < NPAIR; pr += 2048 * 256) {
            int n = pr >> 3;
            int j = idx[pr];
            float d0 = p[j * 3 + 0] - p[n * 3 + 0];
            float d1 = p[j * 3 + 1] - p[n * 3 + 1];
            float d2 = p[j * 3 + 2] - p[n * 3 + 2];
            float y0 = W[0] * d0 + W[1] * d1 + W[2] * d2 + b3[0];
            float y1 = W[3] * d0 + W[4] * d1 + W[5] * d2 + b3[1];
            float y2 = W[6] * d0 + W[7] * d1 + W[8] * d2 + b3[2];
            s0 += y0; q0 += y0 * y0;
            s1 += y1; q1 += y1 * y1;
            s2 += y2; q2 += y2 * y2;
        }
#pragma unroll
        for (int o = 16; o; o >>= 1) {
            s0 += __shfl_xor_sync(FULLM, s0, o);
            s1 += __shfl_xor_sync(FULLM, s1, o);
            s2 += __shfl_xor_sync(FULLM, s2, o);
            q0 += __shfl_xor_sync(FULLM, q0, o);
            q1 += __shfl_xor_sync(FULLM, q1, o);
            q2 += __shfl_xor_sync(FULLM, q2, o);
        }
        __shared__ double sh[6];
        if (tid < 6) sh[tid] = 0.0;
        __syncthreads();
        if ((tid & 31) == 0) {
            atomicAdd(&sh[0], (double)s0);
            atomicAdd(&sh[1], (double)s1);
            atomicAdd(&sh[2], (double)s2);
            atomicAdd(&sh[3], (double)q0);
            atomicAdd(&sh[4], (double)q1);
            atomicAdd(&sh[5], (double)q2);
        }
        __syncthreads();
        if (tid < 6) atomicAdd(&g_acc[tid], sh[tid]);
    }
}

// ---------------- K2: fused t3-gen + wstats  (warp per 2 points) ------------------
__global__ void __launch_bounds__(256, 4) k_wt3(
        const float* __restrict__ p, const int* __restrict__ idx,
        const float* __restrict__ gp, const float* __restrict__ bpv,
        const float* __restrict__ Wp1, const float* __restrict__ bp1,
        const float* __restrict__ Wp2, const float* __restrict__ bp2) {
    __shared__ float s_ap[3], s_cp[3];
    __shared__ double shs[32], shq[32];
    int tid = threadIdx.x, lane = tid & 31, wid = tid >> 5;
    if (tid < 3) {
        double M = (double)NPAIR;
        double m = g_acc[tid] / M;
        double var = g_acc[3 + tid] / M - m * m;
        float a = gp[tid] * rsqrtf((float)var + EPSBN);
        s_ap[tid] = a; s_cp[tid] = bpv[tid] - (float)m * a;
    }
    if (tid < 32) { shs[tid] = 0.0; shq[tid] = 0.0; }
    __syncthreads();
    int pr_i = (lane < 24) ? lane : 23;
    int pair = pr_i / 3, comp = pr_i - pair * 3;
    float wc0 = Wp1[comp * 3 + 0], wc1 = Wp1[comp * 3 + 1], wc2 = Wp1[comp * 3 + 2];
    float b3c = bp1[comp];
    float apc = s_ap[comp], cpc = s_cp[comp];
    float w20 = Wp2[lane * 3 + 0], w21 = Wp2[lane * 3 + 1], w22 = Wp2[lane * 3 + 2];
    float b2 = bp2[lane];
    float s = 0.f, ss = 0.f;
    int gw = blockIdx.x * 8 + wid, nw = gridDim.x * 8;
    for (int n = gw; n < HALF_N; n += nw) {
        int na = n, nb = n + HALF_N;
        int jva = (lane < 8) ? idx[na * 8 + lane] : 0;
        int jvb = (lane < 8) ? idx[nb * 8 + lane] : 0;
        int jma = __shfl_sync(FULLM, jva, pair);
        int jmb = __shfl_sync(FULLM, jvb, pair);
        float pda = p[jma * 3 + comp] - p[na * 3 + comp];
        float pdb = p[jmb * 3 + comp] - p[nb * 3 + comp];
        float a0 = __shfl_sync(FULLM, pda, pair * 3 + 0);
        float a1 = __shfl_sync(FULLM, pda, pair * 3 + 1);
        float a2 = __shfl_sync(FULLM, pda, pair * 3 + 2);
        float b0 = __shfl_sync(FULLM, pdb, pair * 3 + 0);
        float b1 = __shfl_sync(FULLM, pdb, pair * 3 + 1);
        float b2d = __shfl_sync(FULLM, pdb, pair * 3 + 2);
        float ya = wc0 * a0 + wc1 * a1 + wc2 * a2 + b3c;
        float yb = wc0 * b0 + wc1 * b1 + wc2 * b2d + b3c;
        float t3a = fmaxf(0.f, apc * ya + cpc);
        float t3b = fmaxf(0.f, apc * yb + cpc);
        if (lane < 24) {
            g_t3[na * 24 + lane] = t3a;
            g_t3[nb * 24 + lane] = t3b;
        }
        float qa = g_q[na * 32 + lane];
        float qb = g_q[nb * 32 + lane];
#pragma unroll
        for (int ns = 0; ns < 8; ns++) {
            int ja = __shfl_sync(FULLM, jva, ns);
            int jb = __shfl_sync(FULLM, jvb, ns);
            float at0 = __shfl_sync(FULLM, t3a, ns * 3 + 0);
            float at1 = __shfl_sync(FULLM, t3a, ns * 3 + 1);
            float at2 = __shfl_sync(FULLM, t3a, ns * 3 + 2);
            float bt0 = __shfl_sync(FULLM, t3b, ns * 3 + 0);
            float bt1 = __shfl_sync(FULLM, t3b, ns * 3 + 1);
            float bt2 = __shfl_sync(FULLM, t3b, ns * 3 + 2);
            float prca = w20 * at0 + w21 * at1 + w22 * at2 + b2;
            float prcb = w20 * bt0 + w21 * bt1 + w22 * bt2 + b2;
            float wva = g_k[ja * 32 + lane] - qa + prca;
            float wvb = g_k[jb * 32 + lane] - qb + prcb;
            s += wva + wvb; ss += wva * wva + wvb * wvb;
        }
    }
    atomicAdd(&shs[lane], (double)s);
    atomicAdd(&shq[lane], (double)ss);
    __syncthreads();
    if (tid < 32) {
        atomicAdd(&g_acc[6 + tid], shs[tid]);
        atomicAdd(&g_acc[38 + tid], shq[tid]);
    }
}

// ---------------- K3: t = relu(bn_w(w)) @ Ww1.T + bww1 ; warp per 2 points --------
__global__ void __launch_bounds__(256, 4) k_t(
        const int* __restrict__ idx,
        const float* __restrict__ Wp2, const float* __restrict__ bp2,
        const float* __restrict__ gw1, const float* __restrict__ bw1,
        const float* __restrict__ Ww1, const float* __restrict__ bww1) {
    __shared__ float s_aw[32], s_cw[32];
    __shared__ __align__(16) float sw[8][2][8][36];
    __shared__ __align__(16) float sWw1[4 * 36];
    __shared__ double sh[8];
    int tid = threadIdx.x, lane = tid & 31, wid = tid >> 5;
    if (tid < 32) {
        double M = (double)NPAIR;
        double m = g_acc[6 + tid] / M;
        double var = g_acc[38 + tid] / M - m * m;
        float a = gw1[tid] * rsqrtf((float)var + EPSBN);
        s_aw[tid] = a; s_cw[tid] = bw1[tid] - (float)m * a;
    }
    if (tid < 128) sWw1[(tid >> 5) * 36 + (tid & 31)] = Ww1[tid];
    if (tid < 8) sh[tid] = 0.0;
    __syncthreads();
    float aw = s_aw[lane], cw = s_cw[lane];
    float w20 = Wp2[lane * 3 + 0], w21 = Wp2[lane * 3 + 1], w22 = Wp2[lane * 3 + 2];
    float b2 = bp2[lane];
    int m4 = lane & 3, pl = lane >> 2;
    float bm = bww1[m4];
    const float4* wr4 = (const float4*)&sWw1[m4 * 36];
    float sm = 0.f, qm = 0.f;
    int gw = blockIdx.x * 8 + wid, nw = gridDim.x * 8;
    for (int n = gw; n < HALF_N; n += nw) {
        int na = n, nb = n + HALF_N;
        int jva = (lane < 8) ? idx[na * 8 + lane] : 0;
        int jvb = (lane < 8) ? idx[nb * 8 + lane] : 0;
        float t3a = (lane < 24) ? g_t3[na * 24 + lane] : 0.f;
        float t3b = (lane < 24) ? g_t3[nb * 24 + lane] : 0.f;
        float qa = g_q[na * 32 + lane];
        float qb = g_q[nb * 32 + lane];
#pragma unroll
        for (int ns = 0; ns < 8; ns++) {
            int ja = __shfl_sync(FULLM, jva, ns);
            int jb = __shfl_sync(FULLM, jvb, ns);
            float at0 = __shfl_sync(FULLM, t3a, ns * 3 + 0);
            float at1 = __shfl_sync(FULLM, t3a, ns * 3 + 1);
            float at2 = __shfl_sync(FULLM, t3a, ns * 3 + 2);
            float bt0 = __shfl_sync(FULLM, t3b, ns * 3 + 0);
            float bt1 = __shfl_sync(FULLM, t3b, ns * 3 + 1);
            float bt2 = __shfl_sync(FULLM, t3b, ns * 3 + 2);
            float prca = w20 * at0 + w21 * at1 + w22 * at2 + b2;
            float prcb = w20 * bt0 + w21 * bt1 + w22 * bt2 + b2;
            float wva = g_k[ja * 32 + lane] - qa + prca;
            float wvb = g_k[jb * 32 + lane] - qb + prcb;
            sw[wid][0][ns][lane] = fmaxf(0.f, aw * wva + cw);
            sw[wid][1][ns][lane] = fmaxf(0.f, aw * wvb + cw);
        }
        __syncwarp();
        const float4* a4A = (const float4*)&sw[wid][0][pl][0];
        const float4* a4B = (const float4*)&sw[wid][1][pl][0];
        float ta = bm, tb = bm;
#pragma unroll
        for (int c4 = 0; c4 < 8; c4++) {
            float4 aA = a4A[c4], aB = a4B[c4], b4 = wr4[c4];
            ta += aA.x * b4.x + aA.y * b4.y + aA.z * b4.z + aA.w * b4.w;
            tb += aB.x * b4.x + aB.y * b4.y + aB.z * b4.z + aB.w * b4.w;
        }
        g_t[na * 32 + lane] = ta;
        g_t[nb * 32 + lane] = tb;
        sm += ta + tb; qm += ta * ta + tb * tb;
        __syncwarp();
    }
#pragma unroll
    for (int o = 4; o < 32; o <<= 1) {
        sm += __shfl_xor_sync(FULLM, sm, o);
        qm += __shfl_xor_sync(FULLM, qm, o);
    }
    if (lane < 4) {
        atomicAdd(&sh[lane], (double)sm);
        atomicAdd(&sh[4 + lane], (double)qm);
    }
    __syncthreads();
    if (tid < 8) atomicAdd(&g_acc[70 + tid], sh[tid]);
}

// ---------------- K4: softmax + weighted sum -> out  (warp per 2 points) ----------
// lane -> (pair pl = lane>>2, cgroup m4 = lane&3); each lane owns exactly 1 logit
__global__ void __launch_bounds__(256, 4) k_out(
        const int* __restrict__ idx,
        const float* __restrict__ Wp2, const float* __restrict__ bp2,
        const float* __restrict__ gw2, const float* __restrict__ bw2,
        const float* __restrict__ Ww2, const float* __restrict__ bww2,
        float* __restrict__ out) {
    __shared__ float s_at[4], s_ct[4];
    int tid = threadIdx.x, lane = tid & 31, wid = tid >> 5;
    if (tid < 4) {
        double M = (double)NPAIR;
        double m = g_acc[70 + tid] / M;
        double var = g_acc[74 + tid] / M - m * m;
        float a = gw2[tid] * rsqrtf((float)var + EPSBN);
        s_at[tid] = a; s_ct[tid] = bw2[tid] - (float)m * a;
    }
    __syncthreads();
    int m4 = lane & 3, pl = lane >> 2;
    float at0 = s_at[0], at1 = s_at[1], at2 = s_at[2], at3 = s_at[3];
    float ct0 = s_ct[0], ct1 = s_ct[1], ct2 = s_ct[2], ct3 = s_ct[3];
    float v20 = Ww2[m4 * 4 + 0], v21 = Ww2[m4 * 4 + 1];
    float v22 = Ww2[m4 * 4 + 2], v23 = Ww2[m4 * 4 + 3];
    float bcc = bww2[m4];
    float w20 = Wp2[lane * 3 + 0], w21 = Wp2[lane * 3 + 1], w22 = Wp2[lane * 3 + 2];
    float b2 = bp2[lane];
    int gw = blockIdx.x * 8 + wid, nw = gridDim.x * 8;
    for (int n = gw; n < HALF_N; n += nw) {
        int na = n, nb = n + HALF_N;
        int jva = (lane < 8) ? idx[na * 8 + lane] : 0;
        int jvb = (lane < 8) ? idx[nb * 8 + lane] : 0;
        float t3a = (lane < 24) ? g_t3[na * 24 + lane] : 0.f;
        float t3b = (lane < 24) ? g_t3[nb * 24 + lane] : 0.f;
        // per-lane logit: pair pl, channel-group m4
        float4 t4a = *(const float4*)&g_t[na * 32 + pl * 4];
        float4 t4b = *(const float4*)&g_t[nb * 32 + pl * 4];
        float la, lb;
        {
            float u0 = fmaxf(0.f, at0 * t4a.x + ct0);
            float u1 = fmaxf(0.f, at1 * t4a.y + ct1);
            float u2 = fmaxf(0.f, at2 * t4a.z + ct2);
            float u3 = fmaxf(0.f, at3 * t4a.w + ct3);
            la = v20 * u0 + v21 * u1 + v22 * u2 + v23 * u3 + bcc;
            u0 = fmaxf(0.f, at0 * t4b.x + ct0);
            u1 = fmaxf(0.f, at1 * t4b.y + ct1);
            u2 = fmaxf(0.f, at2 * t4b.z + ct2);
            u3 = fmaxf(0.f, at3 * t4b.w + ct3);
            lb = v20 * u0 + v21 * u1 + v22 * u2 + v23 * u3 + bcc;
        }
        // softmax over pairs (8 lanes sharing m4: xor 4, 8, 16)
        float ma = la, mb = lb;
#pragma unroll
        for (int o = 4; o < 32; o <<= 1) {
            ma = fmaxf(ma, __shfl_xor_sync(FULLM, ma, o));
            mb = fmaxf(mb, __shfl_xor_sync(FULLM, mb, o));
        }
        float ea = __expf(la - ma), eb = __expf(lb - mb);
        float sa = ea, sb = eb;
#pragma unroll
        for (int o = 4; o < 32; o <<= 1) {
            sa += __shfl_xor_sync(FULLM, sa, o);
            sb += __shfl_xor_sync(FULLM, sb, o);
        }
        float wna = ea / sa, wnb = eb / sb;
        float oa = 0.f, ob = 0.f;
#pragma unroll
        for (int ns = 0; ns < 8; ns++) {
            int ja = __shfl_sync(FULLM, jva, ns);
            int jb = __shfl_sync(FULLM, jvb, ns);
            float at0s = __shfl_sync(FULLM, t3a, ns * 3 + 0);
            float at1s = __shfl_sync(FULLM, t3a, ns * 3 + 1);
            float at2s = __shfl_sync(FULLM, t3a, ns * 3 + 2);
            float bt0s = __shfl_sync(FULLM, t3b, ns * 3 + 0);
            float bt1s = __shfl_sync(FULLM, t3b, ns * 3 + 1);
            float bt2s = __shfl_sync(FULLM, t3b, ns * 3 + 2);
            float wga = __shfl_sync(FULLM, wna, ns * 4 + m4);
            float wgb = __shfl_sync(FULLM, wnb, ns * 4 + m4);
            float prca = w20 * at0s + w21 * at1s + w22 * at2s + b2;
            float prcb = w20 * bt0s + w21 * bt1s + w22 * bt2s + b2;
            oa += (g_v[ja * 32 + lane] + prca) * wga;
            ob += (g_v[jb * 32 + lane] + prcb) * wgb;
        }
        out[na * 32 + lane] = oa;
        out[nb * 32 + lane] = ob;
    }
}

// ---------------- launch ----------------
extern "C" void kernel_launch(void* const* d_in, const int* in_sizes, int n_in,
                              void* d_out, int out_size) {
    const float* p   = (const float*)d_in[0];
    const float* x   = (const float*)d_in[1];
    const int*   idx = (const int*)d_in[2];
    const float* Wq  = (const float*)d_in[3];  const float* bq   = (const float*)d_in[4];
    const float* Wk  = (const float*)d_in[5];  const float* bk   = (const float*)d_in[6];
    const float* Wv  = (const float*)d_in[7];  const float* bv   = (const float*)d_in[8];
    const float* Wp1 = (const float*)d_in[9];  const float* bp1  = (const float*)d_in[10];
    const float* gp  = (const float*)d_in[11]; const float* bp   = (const float*)d_in[12];
    const float* Wp2 = (const float*)d_in[13]; const float* bp2  = (const float*)d_in[14];
    const float* gw1 = (const float*)d_in[15]; const float* bw1  = (const float*)d_in[16];
    const float* Ww1 = (const float*)d_in[17]; const float* bww1 = (const float*)d_in[18];
    const float* gw2 = (const float*)d_in[19]; const float* bw2  = (const float*)d_in[20];
    const float* Ww2 = (const float*)d_in[21]; const float* bww2 = (const float*)d_in[22];
    float* out = (float*)d_out;

    k_zero<<<1, 128>>>();
    k_fused1<<<QKVB + 2048, 256>>>(p, x, idx, Wq, bq, Wk, bk, Wv, bv, Wp1, bp1);
    k_wt3<<<GATHER_GRID, 256>>>(p, idx, gp, bp, Wp1, bp1, Wp2, bp2);
    k_t<<<GATHER_GRID, 256>>>(idx, Wp2, bp2, gw1, bw1, Ww1, bww1);
    k_out<<<GATHER_GRID, 256>>>(idx, Wp2, bp2, gw2, bw2, Ww2, bww2, out);
}

// round 6
// speedup vs baseline: 3.0913x; 1.0197x over previous
#include <cuda_runtime.h>

#define NPTS 262144
#define NSAMP 8
#define NPAIR (NPTS * NSAMP)
#define HALF_N (NPTS / 2)
#define EPSBN 1e-5f
#define FULLM 0xffffffffu
#define QKVB 1024
#define GATHER_GRID 592   // 4 blocks/SM * 148 SMs

typedef unsigned long long ull;

// ---------------- static device scratch (zero-initialized at module load) --------
__device__ float g_q[NPTS * 32];
__device__ float g_k[NPTS * 32];
__device__ float g_v[NPTS * 32];
__device__ float g_t3[NPAIR * 3];   // relu(bn_p(p_r @ Wp1.T + bp1)) per pair (24 MB)
__device__ float g_t[NPAIR * 4];    // t pre-BN (32 MB)
// [0..2] psum [3..5] psq  [6..37] wsum [38..69] wsq  [70..73] tsum [74..77] tsq
__device__ double g_acc[78];
__device__ unsigned int g_ctr;

// ---------------- f32x2 packed-FMA helpers ----------------
__device__ __forceinline__ void ffma2(ull &acc, ull a, ull b) {
    asm("fma.rn.f32x2 %0, %1, %2, %0;" : "+l"(acc) : "l"(a), "l"(b));
}
__device__ __forceinline__ ull pack2(float x) {
    ull r;
    asm("mov.b64 %0, {%1, %1};" : "=l"(r) : "f"(x));
    return r;
}
__device__ __forceinline__ void unpack2(ull v, float &lo, float &hi) {
    asm("mov.b64 {%0, %1}, %2;" : "=f"(lo), "=f"(hi) : "l"(v));
}

// ---------------- K1: fused qkv (blocks 0..QKVB-1, f32x2) + pstats ---------------
__global__ void __launch_bounds__(256) k_fused1(
        const float* __restrict__ p, const float* __restrict__ x,
        const int* __restrict__ idx,
        const float* __restrict__ Wq, const float* __restrict__ bq,
        const float* __restrict__ Wk, const float* __restrict__ bk,
        const float* __restrict__ Wv, const float* __restrict__ bv,
        const float* __restrict__ Wp1, const float* __restrict__ bp1) {
    int tid = threadIdx.x;
    if (blockIdx.x < QKVB) {
        // ---- qkv: warp handles 8 points/chunk as 4 f32x2 pairs ----
        __shared__ float sW[3][1024];
        __shared__ ull sx2[8][4][32];
        __shared__ float sb[3][32];
        for (int e = tid; e < 1024; e += 256) {
            int c = e >> 5, i = e & 31;
            sW[0][i * 32 + c] = Wq[e];
            sW[1][i * 32 + c] = Wk[e];
            sW[2][i * 32 + c] = Wv[e];
        }
        if (tid < 32) { sb[0][tid] = bq[tid]; sb[1][tid] = bk[tid]; sb[2][tid] = bv[tid]; }
        __syncthreads();
        int wid = tid >> 5, lane = tid & 31;
        ull bias2[3] = { pack2(sb[0][lane]), pack2(sb[1][lane]), pack2(sb[2][lane]) };
        float* sxf = (float*)&sx2[wid][0][0];
        for (int chunk = blockIdx.x; chunk < NPTS / 64; chunk += QKVB) {
            int n0 = chunk * 64 + wid * 8;
#pragma unroll
            for (int pp = 0; pp < 8; pp++) {
                float v = x[(n0 + pp) * 32 + lane];
                sxf[((pp >> 1) * 32 + lane) * 2 + (pp & 1)] = v;
            }
            __syncwarp();
            ull acc[3][4];
#pragma unroll
            for (int m = 0; m < 3; m++)
#pragma unroll
                for (int pr = 0; pr < 4; pr++) acc[m][pr] = bias2[m];
#pragma unroll 4
            for (int i = 0; i < 32; i++) {
                ull w0 = pack2(sW[0][i * 32 + lane]);
                ull w1 = pack2(sW[1][i * 32 + lane]);
                ull w2 = pack2(sW[2][i * 32 + lane]);
#pragma unroll
                for (int pr = 0; pr < 4; pr++) {
                    ull xp = sx2[wid][pr][i];
                    ffma2(acc[0][pr], w0, xp);
                    ffma2(acc[1][pr], w1, xp);
                    ffma2(acc[2][pr], w2, xp);
                }
            }
#pragma unroll
            for (int pr = 0; pr < 4; pr++) {
                float lo, hi;
                unpack2(acc[0][pr], lo, hi);
                g_q[(n0 + 2 * pr) * 32 + lane] = lo;
                g_q[(n0 + 2 * pr + 1) * 32 + lane] = hi;
                unpack2(acc[1][pr], lo, hi);
                g_k[(n0 + 2 * pr) * 32 + lane] = lo;
                g_k[(n0 + 2 * pr + 1) * 32 + lane] = hi;
                unpack2(acc[2][pr], lo, hi);
                g_v[(n0 + 2 * pr) * 32 + lane] = lo;
                g_v[(n0 + 2 * pr + 1) * 32 + lane] = hi;
            }
            __syncwarp();
        }
    } else {
        // ---- pstats: grid-stride over pairs ----
        float W[9], b3[3];
#pragma unroll
        for (int i = 0; i < 9; i++) W[i] = Wp1[i];
#pragma unroll
        for (int i = 0; i < 3; i++) b3[i] = bp1[i];
        float s0 = 0, s1 = 0, s2 = 0, q0 = 0, q1 = 0, q2 = 0;
        int bid = blockIdx.x - QKVB;
        for (int pr = bid * 256 + tid; pr < NPAIR; pr += 2048 * 256) {
            int n = pr >> 3;
            int j = __ldg(&idx[pr]);
            float d0 = __ldg(&p[j * 3 + 0]) - __ldg(&p[n * 3 + 0]);
            float d1 = __ldg(&p[j * 3 + 1]) - __ldg(&p[n * 3 + 1]);
            float d2 = __ldg(&p[j * 3 + 2]) - __ldg(&p[n * 3 + 2]);
            float y0 = W[0] * d0 + W[1] * d1 + W[2] * d2 + b3[0];
            float y1 = W[3] * d0 + W[4] * d1 + W[5] * d2 + b3[1];
            float y2 = W[6] * d0 + W[7] * d1 + W[8] * d2 + b3[2];
            s0 += y0; q0 += y0 * y0;
            s1 += y1; q1 += y1 * y1;
            s2 += y2; q2 += y2 * y2;
        }
#pragma unroll
        for (int o = 16; o; o >>= 1) {
            s0 += __shfl_xor_sync(FULLM, s0, o);
            s1 += __shfl_xor_sync(FULLM, s1, o);
            s2 += __shfl_xor_sync(FULLM, s2, o);
            q0 += __shfl_xor_sync(FULLM, q0, o);
            q1 += __shfl_xor_sync(FULLM, q1, o);
            q2 += __shfl_xor_sync(FULLM, q2, o);
        }
        __shared__ double sh[6];
        if (tid < 6) sh[tid] = 0.0;
        __syncthreads();
        if ((tid & 31) == 0) {
            atomicAdd(&sh[0], (double)s0);
            atomicAdd(&sh[1], (double)s1);
            atomicAdd(&sh[2], (double)s2);
            atomicAdd(&sh[3], (double)q0);
            atomicAdd(&sh[4], (double)q1);
            atomicAdd(&sh[5], (double)q2);
        }
        __syncthreads();
        if (tid < 6) atomicAdd(&g_acc[tid], sh[tid]);
    }
}

// ---------------- K2: fused t3-gen + wstats  (warp per 2 points, prefetch) -------
__global__ void __launch_bounds__(256, 4) k_wt3(
        const float* __restrict__ p, const int* __restrict__ idx,
        const float* __restrict__ gp, const float* __restrict__ bpv,
        const float* __restrict__ Wp1, const float* __restrict__ bp1,
        const float* __restrict__ Wp2, const float* __restrict__ bp2) {
    __shared__ float s_ap[3], s_cp[3];
    __shared__ double shs[32], shq[32];
    int tid = threadIdx.x, lane = tid & 31, wid = tid >> 5;
    if (tid < 3) {
        double M = (double)NPAIR;
        double m = g_acc[tid] / M;
        double var = g_acc[3 + tid] / M - m * m;
        float a = gp[tid] * rsqrtf((float)var + EPSBN);
        s_ap[tid] = a; s_cp[tid] = bpv[tid] - (float)m * a;
    }
    if (tid < 32) { shs[tid] = 0.0; shq[tid] = 0.0; }
    __syncthreads();
    int pr_i = (lane < 24) ? lane : 23;
    int pair = pr_i / 3, comp = pr_i - pair * 3;
    float wc0 = Wp1[comp * 3 + 0], wc1 = Wp1[comp * 3 + 1], wc2 = Wp1[comp * 3 + 2];
    float b3c = bp1[comp];
    float apc = s_ap[comp], cpc = s_cp[comp];
    float w20 = Wp2[lane * 3 + 0], w21 = Wp2[lane * 3 + 1], w22 = Wp2[lane * 3 + 2];
    float b2 = bp2[lane];
    float s = 0.f, ss = 0.f;
    int gw = blockIdx.x * 8 + wid, nw = gridDim.x * 8;
    int n = gw;
    int jva = 0, jvb = 0; float qa = 0.f, qb = 0.f;
    if (n < HALF_N) {
        jva = (lane < 8) ? __ldg(&idx[n * 8 + lane]) : 0;
        jvb = (lane < 8) ? __ldg(&idx[(n + HALF_N) * 8 + lane]) : 0;
        qa = __ldg(&g_q[n * 32 + lane]);
        qb = __ldg(&g_q[(n + HALF_N) * 32 + lane]);
    }
    while (n < HALF_N) {
        int n2 = n + nw;
        int n2c = (n2 < HALF_N) ? n2 : gw;
        int jva_n = (lane < 8) ? __ldg(&idx[n2c * 8 + lane]) : 0;
        int jvb_n = (lane < 8) ? __ldg(&idx[(n2c + HALF_N) * 8 + lane]) : 0;
        float qa_n = __ldg(&g_q[n2c * 32 + lane]);
        float qb_n = __ldg(&g_q[(n2c + HALF_N) * 32 + lane]);
        int na = n, nb = n + HALF_N;
        // t3 generation (store deferred to after gather loop)
        int jma = __shfl_sync(FULLM, jva, pair);
        int jmb = __shfl_sync(FULLM, jvb, pair);
        float pda = __ldg(&p[jma * 3 + comp]) - __ldg(&p[na * 3 + comp]);
        float pdb = __ldg(&p[jmb * 3 + comp]) - __ldg(&p[nb * 3 + comp]);
        float a0 = __shfl_sync(FULLM, pda, pair * 3 + 0);
        float a1 = __shfl_sync(FULLM, pda, pair * 3 + 1);
        float a2 = __shfl_sync(FULLM, pda, pair * 3 + 2);
        float b0 = __shfl_sync(FULLM, pdb, pair * 3 + 0);
        float b1 = __shfl_sync(FULLM, pdb, pair * 3 + 1);
        float b2d = __shfl_sync(FULLM, pdb, pair * 3 + 2);
        float ya = wc0 * a0 + wc1 * a1 + wc2 * a2 + b3c;
        float yb = wc0 * b0 + wc1 * b1 + wc2 * b2d + b3c;
        float t3a = fmaxf(0.f, apc * ya + cpc);
        float t3b = fmaxf(0.f, apc * yb + cpc);
#pragma unroll
        for (int ns = 0; ns < 8; ns++) {
            int ja = __shfl_sync(FULLM, jva, ns);
            int jb = __shfl_sync(FULLM, jvb, ns);
            float kva = __ldg(&g_k[ja * 32 + lane]);
            float kvb = __ldg(&g_k[jb * 32 + lane]);
            float at0 = __shfl_sync(FULLM, t3a, ns * 3 + 0);
            float at1 = __shfl_sync(FULLM, t3a, ns * 3 + 1);
            float at2 = __shfl_sync(FULLM, t3a, ns * 3 + 2);
            float bt0 = __shfl_sync(FULLM, t3b, ns * 3 + 0);
            float bt1 = __shfl_sync(FULLM, t3b, ns * 3 + 1);
            float bt2 = __shfl_sync(FULLM, t3b, ns * 3 + 2);
            float prca = w20 * at0 + w21 * at1 + w22 * at2 + b2;
            float prcb = w20 * bt0 + w21 * bt1 + w22 * bt2 + b2;
            float wva = kva - qa + prca;
            float wvb = kvb - qb + prcb;
            s += wva + wvb; ss += wva * wva + wvb * wvb;
        }
        if (lane < 24) {
            g_t3[na * 24 + lane] = t3a;
            g_t3[nb * 24 + lane] = t3b;
        }
        n = n2; jva = jva_n; jvb = jvb_n; qa = qa_n; qb = qb_n;
    }
    atomicAdd(&shs[lane], (double)s);
    atomicAdd(&shq[lane], (double)ss);
    __syncthreads();
    if (tid < 32) {
        atomicAdd(&g_acc[6 + tid], shs[tid]);
        atomicAdd(&g_acc[38 + tid], shq[tid]);
    }
}

// ---------------- K3: t = relu(bn_w(w)) @ Ww1.T + bww1 (warp/2pts, prefetch) -----
__global__ void __launch_bounds__(256, 4) k_t(
        const int* __restrict__ idx,
        const float* __restrict__ Wp2, const float* __restrict__ bp2,
        const float* __restrict__ gw1, const float* __restrict__ bw1,
        const float* __restrict__ Ww1, const float* __restrict__ bww1) {
    __shared__ float s_aw[32], s_cw[32];
    __shared__ __align__(16) float sw[8][2][8][36];
    __shared__ __align__(16) float sWw1[4 * 36];
    __shared__ double sh[8];
    int tid = threadIdx.x, lane = tid & 31, wid = tid >> 5;
    if (tid < 32) {
        double M = (double)NPAIR;
        double m = g_acc[6 + tid] / M;
        double var = g_acc[38 + tid] / M - m * m;
        float a = gw1[tid] * rsqrtf((float)var + EPSBN);
        s_aw[tid] = a; s_cw[tid] = bw1[tid] - (float)m * a;
    }
    if (tid < 128) sWw1[(tid >> 5) * 36 + (tid & 31)] = Ww1[tid];
    if (tid < 8) sh[tid] = 0.0;
    __syncthreads();
    float aw = s_aw[lane], cw = s_cw[lane];
    float w20 = Wp2[lane * 3 + 0], w21 = Wp2[lane * 3 + 1], w22 = Wp2[lane * 3 + 2];
    float b2 = bp2[lane];
    int m4 = lane & 3, pl = lane >> 2;
    float bm = bww1[m4];
    const float4* wr4 = (const float4*)&sWw1[m4 * 36];
    float sm = 0.f, qm = 0.f;
    int gw = blockIdx.x * 8 + wid, nw = gridDim.x * 8;
    int n = gw;
    int jva = 0, jvb = 0; float t3a = 0.f, t3b = 0.f, qa = 0.f, qb = 0.f;
    if (n < HALF_N) {
        jva = (lane < 8) ? __ldg(&idx[n * 8 + lane]) : 0;
        jvb = (lane < 8) ? __ldg(&idx[(n + HALF_N) * 8 + lane]) : 0;
        t3a = (lane < 24) ? __ldg(&g_t3[n * 24 + lane]) : 0.f;
        t3b = (lane < 24) ? __ldg(&g_t3[(n + HALF_N) * 24 + lane]) : 0.f;
        qa = __ldg(&g_q[n * 32 + lane]);
        qb = __ldg(&g_q[(n + HALF_N) * 32 + lane]);
    }
    while (n < HALF_N) {
        int n2 = n + nw;
        int n2c = (n2 < HALF_N) ? n2 : gw;
        int jva_n = (lane < 8) ? __ldg(&idx[n2c * 8 + lane]) : 0;
        int jvb_n = (lane < 8) ? __ldg(&idx[(n2c + HALF_N) * 8 + lane]) : 0;
        float t3a_n = (lane < 24) ? __ldg(&g_t3[n2c * 24 + lane]) : 0.f;
        float t3b_n = (lane < 24) ? __ldg(&g_t3[(n2c + HALF_N) * 24 + lane]) : 0.f;
        float qa_n = __ldg(&g_q[n2c * 32 + lane]);
        float qb_n = __ldg(&g_q[(n2c + HALF_N) * 32 + lane]);
        int na = n, nb = n + HALF_N;
#pragma unroll
        for (int ns = 0; ns < 8; ns++) {
            int ja = __shfl_sync(FULLM, jva, ns);
            int jb = __shfl_sync(FULLM, jvb, ns);
            float kva = __ldg(&g_k[ja * 32 + lane]);
            float kvb = __ldg(&g_k[jb * 32 + lane]);
            float at0 = __shfl_sync(FULLM, t3a, ns * 3 + 0);
            float at1 = __shfl_sync(FULLM, t3a, ns * 3 + 1);
            float at2 = __shfl_sync(FULLM, t3a, ns * 3 + 2);
            float bt0 = __shfl_sync(FULLM, t3b, ns * 3 + 0);
            float bt1 = __shfl_sync(FULLM, t3b, ns * 3 + 1);
            float bt2 = __shfl_sync(FULLM, t3b, ns * 3 + 2);
            float prca = w20 * at0 + w21 * at1 + w22 * at2 + b2;
            float prcb = w20 * bt0 + w21 * bt1 + w22 * bt2 + b2;
            float wva = kva - qa + prca;
            float wvb = kvb - qb + prcb;
            sw[wid][0][ns][lane] = fmaxf(0.f, aw * wva + cw);
            sw[wid][1][ns][lane] = fmaxf(0.f, aw * wvb + cw);
        }
        __syncwarp();
        const float4* a4A = (const float4*)&sw[wid][0][pl][0];
        const float4* a4B = (const float4*)&sw[wid][1][pl][0];
        float ta = bm, tb = bm;
#pragma unroll
        for (int c4 = 0; c4 < 8; c4++) {
            float4 aA = a4A[c4], aB = a4B[c4], b4 = wr4[c4];
            ta += aA.x * b4.x + aA.y * b4.y + aA.z * b4.z + aA.w * b4.w;
            tb += aB.x * b4.x + aB.y * b4.y + aB.z * b4.z + aB.w * b4.w;
        }
        g_t[na * 32 + lane] = ta;
        g_t[nb * 32 + lane] = tb;
        sm += ta + tb; qm += ta * ta + tb * tb;
        __syncwarp();
        n = n2; jva = jva_n; jvb = jvb_n; t3a = t3a_n; t3b = t3b_n; qa = qa_n; qb = qb_n;
    }
#pragma unroll
    for (int o = 4; o < 32; o <<= 1) {
        sm += __shfl_xor_sync(FULLM, sm, o);
        qm += __shfl_xor_sync(FULLM, qm, o);
    }
    if (lane < 4) {
        atomicAdd(&sh[lane], (double)sm);
        atomicAdd(&sh[4 + lane], (double)qm);
    }
    __syncthreads();
    if (tid < 8) atomicAdd(&g_acc[70 + tid], sh[tid]);
}

// ---------------- K4: softmax + weighted sum -> out  (warp/2pts, prefetch) --------
__global__ void __launch_bounds__(256, 4) k_out(
        const int* __restrict__ idx,
        const float* __restrict__ Wp2, const float* __restrict__ bp2,
        const float* __restrict__ gw2, const float* __restrict__ bw2,
        const float* __restrict__ Ww2, const float* __restrict__ bww2,
        float* __restrict__ out) {
    __shared__ float s_at[4], s_ct[4];
    int tid = threadIdx.x, lane = tid & 31, wid = tid >> 5;
    if (tid < 4) {
        double M = (double)NPAIR;
        double m = g_acc[70 + tid] / M;
        double var = g_acc[74 + tid] / M - m * m;
        float a = gw2[tid] * rsqrtf((float)var + EPSBN);
        s_at[tid] = a; s_ct[tid] = bw2[tid] - (float)m * a;
    }
    __syncthreads();
    int m4 = lane & 3, pl = lane >> 2;
    float at0 = s_at[0], at1 = s_at[1], at2 = s_at[2], at3 = s_at[3];
    float ct0 = s_ct[0], ct1 = s_ct[1], ct2 = s_ct[2], ct3 = s_ct[3];
    float v20 = Ww2[m4 * 4 + 0], v21 = Ww2[m4 * 4 + 1];
    float v22 = Ww2[m4 * 4 + 2], v23 = Ww2[m4 * 4 + 3];
    float bcc = bww2[m4];
    float w20 = Wp2[lane * 3 + 0], w21 = Wp2[lane * 3 + 1], w22 = Wp2[lane * 3 + 2];
    float b2 = bp2[lane];
    int gw = blockIdx.x * 8 + wid, nw = gridDim.x * 8;
    int n = gw;
    int jva = 0, jvb = 0; float t3a = 0.f, t3b = 0.f;
    float4 t4a = {0, 0, 0, 0}, t4b = {0, 0, 0, 0};
    if (n < HALF_N) {
        jva = (lane < 8) ? __ldg(&idx[n * 8 + lane]) : 0;
        jvb = (lane < 8) ? __ldg(&idx[(n + HALF_N) * 8 + lane]) : 0;
        t3a = (lane < 24) ? __ldg(&g_t3[n * 24 + lane]) : 0.f;
        t3b = (lane < 24) ? __ldg(&g_t3[(n + HALF_N) * 24 + lane]) : 0.f;
        t4a = __ldg((const float4*)&g_t[n * 32 + pl * 4]);
        t4b = __ldg((const float4*)&g_t[(n + HALF_N) * 32 + pl * 4]);
    }
    while (n < HALF_N) {
        int n2 = n + nw;
        int n2c = (n2 < HALF_N) ? n2 : gw;
        int jva_n = (lane < 8) ? __ldg(&idx[n2c * 8 + lane]) : 0;
        int jvb_n = (lane < 8) ? __ldg(&idx[(n2c + HALF_N) * 8 + lane]) : 0;
        float t3a_n = (lane < 24) ? __ldg(&g_t3[n2c * 24 + lane]) : 0.f;
        float t3b_n = (lane < 24) ? __ldg(&g_t3[(n2c + HALF_N) * 24 + lane]) : 0.f;
        float4 t4a_n = __ldg((const float4*)&g_t[n2c * 32 + pl * 4]);
        float4 t4b_n = __ldg((const float4*)&g_t[(n2c + HALF_N) * 32 + pl * 4]);
        int na = n, nb = n + HALF_N;
        float la, lb;
        {
            float u0 = fmaxf(0.f, at0 * t4a.x + ct0);
            float u1 = fmaxf(0.f, at1 * t4a.y + ct1);
            float u2 = fmaxf(0.f, at2 * t4a.z + ct2);
            float u3 = fmaxf(0.f, at3 * t4a.w + ct3);
            la = v20 * u0 + v21 * u1 + v22 * u2 + v23 * u3 + bcc;
            u0 = fmaxf(0.f, at0 * t4b.x + ct0);
            u1 = fmaxf(0.f, at1 * t4b.y + ct1);
            u2 = fmaxf(0.f, at2 * t4b.z + ct2);
            u3 = fmaxf(0.f, at3 * t4b.w + ct3);
            lb = v20 * u0 + v21 * u1 + v22 * u2 + v23 * u3 + bcc;
        }
        float ma = la, mb = lb;
#pragma unroll
        for (int o = 4; o < 32; o <<= 1) {
            ma = fmaxf(ma, __shfl_xor_sync(FULLM, ma, o));
            mb = fmaxf(mb, __shfl_xor_sync(FULLM, mb, o));
        }
        float ea = __expf(la - ma), eb = __expf(lb - mb);
        float sa = ea, sb = eb;
#pragma unroll
        for (int o = 4; o < 32; o <<= 1) {
            sa += __shfl_xor_sync(FULLM, sa, o);
            sb += __shfl_xor_sync(FULLM, sb, o);
        }
        float wna = ea / sa, wnb = eb / sb;
        float oa = 0.f, ob = 0.f;
#pragma unroll
        for (int ns = 0; ns < 8; ns++) {
            int ja = __shfl_sync(FULLM, jva, ns);
            int jb = __shfl_sync(FULLM, jvb, ns);
            float vva = __ldg(&g_v[ja * 32 + lane]);
            float vvb = __ldg(&g_v[jb * 32 + lane]);
            float at0s = __shfl_sync(FULLM, t3a, ns * 3 + 0);
            float at1s = __shfl_sync(FULLM, t3a, ns * 3 + 1);
            float at2s = __shfl_sync(FULLM, t3a, ns * 3 + 2);
            float bt0s = __shfl_sync(FULLM, t3b, ns * 3 + 0);
            float bt1s = __shfl_sync(FULLM, t3b, ns * 3 + 1);
            float bt2s = __shfl_sync(FULLM, t3b, ns * 3 + 2);
            float wga = __shfl_sync(FULLM, wna, ns * 4 + m4);
            float wgb = __shfl_sync(FULLM, wnb, ns * 4 + m4);
            float prca = w20 * at0s + w21 * at1s + w22 * at2s + b2;
            float prcb = w20 * bt0s + w21 * bt1s + w22 * bt2s + b2;
            oa += (vva + prca) * wga;
            ob += (vvb + prcb) * wgb;
        }
        out[na * 32 + lane] = oa;
        out[nb * 32 + lane] = ob;
        n = n2; jva = jva_n; jvb = jvb_n; t3a = t3a_n; t3b = t3b_n; t4a = t4a_n; t4b = t4b_n;
    }
    // last-finishing block re-zeroes g_acc for the next launch (replaces k_zero)
    __syncthreads();
    if (tid == 0) {
        __threadfence();
        unsigned int tk = atomicAdd(&g_ctr, 1u);
        if (tk == gridDim.x - 1) {
            for (int i = 0; i < 78; i++) g_acc[i] = 0.0;
            g_ctr = 0u;
        }
    }
}

// ---------------- launch ----------------
extern "C" void kernel_launch(void* const* d_in, const int* in_sizes, int n_in,
                              void* d_out, int out_size) {
    const float* p   = (const float*)d_in[0];
    const float* x   = (const float*)d_in[1];
    const int*   idx = (const int*)d_in[2];
    const float* Wq  = (const float*)d_in[3];  const float* bq   = (const float*)d_in[4];
    const float* Wk  = (const float*)d_in[5];  const float* bk   = (const float*)d_in[6];
    const float* Wv  = (const float*)d_in[7];  const float* bv   = (const float*)d_in[8];
    const float* Wp1 = (const float*)d_in[9];  const float* bp1  = (const float*)d_in[10];
    const float* gp  = (const float*)d_in[11]; const float* bp   = (const float*)d_in[12];
    const float* Wp2 = (const float*)d_in[13]; const float* bp2  = (const float*)d_in[14];
    const float* gw1 = (const float*)d_in[15]; const float* bw1  = (const float*)d_in[16];
    const float* Ww1 = (const float*)d_in[17]; const float* bww1 = (const float*)d_in[18];
    const float* gw2 = (const float*)d_in[19]; const float* bw2  = (const float*)d_in[20];
    const float* Ww2 = (const float*)d_in[21]; const float* bww2 = (const float*)d_in[22];
    float* out = (float*)d_out;

    k_fused1<<<QKVB + 2048, 256>>>(p, x, idx, Wq, bq, Wk, bk, Wv, bv, Wp1, bp1);
    k_wt3<<<GATHER_GRID, 256>>>(p, idx, gp, bp, Wp1, bp1, Wp2, bp2);
    k_t<<<GATHER_GRID, 256>>>(idx, Wp2, bp2, gw1, bw1, Ww1, bww1);
    k_out<<<GATHER_GRID, 256>>>(idx, Wp2, bp2, gw2, bw2, Ww2, bww2, out);
}

// round 7
// speedup vs baseline: 3.1254x; 1.0110x over previous
#include <cuda_runtime.h>

#define NPTS 262144
#define NSAMP 8
#define NPAIR (NPTS * NSAMP)
#define HALF_N (NPTS / 2)
#define EPSBN 1e-5f
#define FULLM 0xffffffffu
#define QKVB 1024
#define GATHER_GRID 592   // 4 blocks/SM * 148 SMs
#define OUT_GRID 740      // 5 blocks/SM * 148 SMs

typedef unsigned long long ull;

// ---------------- static device scratch (zero-initialized at module load) --------
__device__ float g_q[NPTS * 32];
__device__ float g_k[NPTS * 32];
__device__ float g_v[NPTS * 32];
__device__ float g_t3[NPAIR * 3];   // relu(bn_p(p_r @ Wp1.T + bp1)) per pair (24 MB)
__device__ float g_t[NPAIR * 4];    // t pre-BN (32 MB)
// [0..2] psum [3..5] psq  [6..37] wsum [38..69] wsq  [70..73] tsum [74..77] tsq
__device__ double g_acc[78];
__device__ unsigned int g_ctr;

// ---------------- f32x2 packed-FMA helpers ----------------
__device__ __forceinline__ void ffma2(ull &acc, ull a, ull b) {
    asm("fma.rn.f32x2 %0, %1, %2, %0;" : "+l"(acc) : "l"(a), "l"(b));
}
__device__ __forceinline__ ull pack2(float x) {
    ull r;
    asm("mov.b64 %0, {%1, %1};" : "=l"(r) : "f"(x));
    return r;
}
__device__ __forceinline__ void unpack2(ull v, float &lo, float &hi) {
    asm("mov.b64 {%0, %1}, %2;" : "=f"(lo), "=f"(hi) : "l"(v));
}

// ---------------- K1: fused qkv (blocks 0..QKVB-1, f32x2) + pstats ---------------
__global__ void __launch_bounds__(256) k_fused1(
        const float* __restrict__ p, const float* __restrict__ x,
        const int* __restrict__ idx,
        const float* __restrict__ Wq, const float* __restrict__ bq,
        const float* __restrict__ Wk, const float* __restrict__ bk,
        const float* __restrict__ Wv, const float* __restrict__ bv,
        const float* __restrict__ Wp1, const float* __restrict__ bp1) {
    int tid = threadIdx.x;
    if (blockIdx.x < QKVB) {
        __shared__ float sW[3][1024];
        __shared__ ull sx2[8][4][32];
        __shared__ float sb[3][32];
        for (int e = tid; e < 1024; e += 256) {
            int c = e >> 5, i = e & 31;
            sW[0][i * 32 + c] = Wq[e];
            sW[1][i * 32 + c] = Wk[e];
            sW[2][i * 32 + c] = Wv[e];
        }
        if (tid < 32) { sb[0][tid] = bq[tid]; sb[1][tid] = bk[tid]; sb[2][tid] = bv[tid]; }
        __syncthreads();
        int wid = tid >> 5, lane = tid & 31;
        ull bias2[3] = { pack2(sb[0][lane]), pack2(sb[1][lane]), pack2(sb[2][lane]) };
        float* sxf = (float*)&sx2[wid][0][0];
        for (int chunk = blockIdx.x; chunk < NPTS / 64; chunk += QKVB) {
            int n0 = chunk * 64 + wid * 8;
#pragma unroll
            for (int pp = 0; pp < 8; pp++) {
                float v = x[(n0 + pp) * 32 + lane];
                sxf[((pp >> 1) * 32 + lane) * 2 + (pp & 1)] = v;
            }
            __syncwarp();
            ull acc[3][4];
#pragma unroll
            for (int m = 0; m < 3; m++)
#pragma unroll
                for (int pr = 0; pr < 4; pr++) acc[m][pr] = bias2[m];
#pragma unroll 4
            for (int i = 0; i < 32; i++) {
                ull w0 = pack2(sW[0][i * 32 + lane]);
                ull w1 = pack2(sW[1][i * 32 + lane]);
                ull w2 = pack2(sW[2][i * 32 + lane]);
#pragma unroll
                for (int pr = 0; pr < 4; pr++) {
                    ull xp = sx2[wid][pr][i];
                    ffma2(acc[0][pr], w0, xp);
                    ffma2(acc[1][pr], w1, xp);
                    ffma2(acc[2][pr], w2, xp);
                }
            }
#pragma unroll
            for (int pr = 0; pr < 4; pr++) {
                float lo, hi;
                unpack2(acc[0][pr], lo, hi);
                g_q[(n0 + 2 * pr) * 32 + lane] = lo;
                g_q[(n0 + 2 * pr + 1) * 32 + lane] = hi;
                unpack2(acc[1][pr], lo, hi);
                g_k[(n0 + 2 * pr) * 32 + lane] = lo;
                g_k[(n0 + 2 * pr + 1) * 32 + lane] = hi;
                unpack2(acc[2][pr], lo, hi);
                g_v[(n0 + 2 * pr) * 32 + lane] = lo;
                g_v[(n0 + 2 * pr + 1) * 32 + lane] = hi;
            }
            __syncwarp();
        }
    } else {
        float W[9], b3[3];
#pragma unroll
        for (int i = 0; i < 9; i++) W[i] = Wp1[i];
#pragma unroll
        for (int i = 0; i < 3; i++) b3[i] = bp1[i];
        float s0 = 0, s1 = 0, s2 = 0, q0 = 0, q1 = 0, q2 = 0;
        int bid = blockIdx.x - QKVB;
        for (int pr = bid * 256 + tid; pr < NPAIR; pr += 2048 * 256) {
            int n = pr >> 3;
            int j = __ldg(&idx[pr]);
            float d0 = __ldg(&p[j * 3 + 0]) - __ldg(&p[n * 3 + 0]);
            float d1 = __ldg(&p[j * 3 + 1]) - __ldg(&p[n * 3 + 1]);
            float d2 = __ldg(&p[j * 3 + 2]) - __ldg(&p[n * 3 + 2]);
            float y0 = W[0] * d0 + W[1] * d1 + W[2] * d2 + b3[0];
            float y1 = W[3] * d0 + W[4] * d1 + W[5] * d2 + b3[1];
            float y2 = W[6] * d0 + W[7] * d1 + W[8] * d2 + b3[2];
            s0 += y0; q0 += y0 * y0;
            s1 += y1; q1 += y1 * y1;
            s2 += y2; q2 += y2 * y2;
        }
#pragma unroll
        for (int o = 16; o; o >>= 1) {
            s0 += __shfl_xor_sync(FULLM, s0, o);
            s1 += __shfl_xor_sync(FULLM, s1, o);
            s2 += __shfl_xor_sync(FULLM, s2, o);
            q0 += __shfl_xor_sync(FULLM, q0, o);
            q1 += __shfl_xor_sync(FULLM, q1, o);
            q2 += __shfl_xor_sync(FULLM, q2, o);
        }
        __shared__ double sh[6];
        if (tid < 6) sh[tid] = 0.0;
        __syncthreads();
        if ((tid & 31) == 0) {
            atomicAdd(&sh[0], (double)s0);
            atomicAdd(&sh[1], (double)s1);
            atomicAdd(&sh[2], (double)s2);
            atomicAdd(&sh[3], (double)q0);
            atomicAdd(&sh[4], (double)q1);
            atomicAdd(&sh[5], (double)q2);
        }
        __syncthreads();
        if (tid < 6) atomicAdd(&g_acc[tid], sh[tid]);
    }
}

// ---------------- K2: fused t3-gen + wstats  (warp per 2 points, prefetch) -------
__global__ void __launch_bounds__(256, 4) k_wt3(
        const float* __restrict__ p, const int* __restrict__ idx,
        const float* __restrict__ gp, const float* __restrict__ bpv,
        const float* __restrict__ Wp1, const float* __restrict__ bp1,
        const float* __restrict__ Wp2, const float* __restrict__ bp2) {
    __shared__ float s_ap[3], s_cp[3];
    __shared__ double shs[32], shq[32];
    int tid = threadIdx.x, lane = tid & 31, wid = tid >> 5;
    if (tid < 3) {
        double M = (double)NPAIR;
        double m = g_acc[tid] / M;
        double var = g_acc[3 + tid] / M - m * m;
        float a = gp[tid] * rsqrtf((float)var + EPSBN);
        s_ap[tid] = a; s_cp[tid] = bpv[tid] - (float)m * a;
    }
    if (tid < 32) { shs[tid] = 0.0; shq[tid] = 0.0; }
    __syncthreads();
    int pr_i = (lane < 24) ? lane : 23;
    int pair = pr_i / 3, comp = pr_i - pair * 3;
    float wc0 = Wp1[comp * 3 + 0], wc1 = Wp1[comp * 3 + 1], wc2 = Wp1[comp * 3 + 2];
    float b3c = bp1[comp];
    float apc = s_ap[comp], cpc = s_cp[comp];
    float w20 = Wp2[lane * 3 + 0], w21 = Wp2[lane * 3 + 1], w22 = Wp2[lane * 3 + 2];
    float b2 = bp2[lane];
    float s = 0.f, ss = 0.f;
    int gw = blockIdx.x * 8 + wid, nw = gridDim.x * 8;
    int n = gw;
    int jva = 0, jvb = 0; float qa = 0.f, qb = 0.f;
    if (n < HALF_N) {
        jva = (lane < 8) ? __ldg(&idx[n * 8 + lane]) : 0;
        jvb = (lane < 8) ? __ldg(&idx[(n + HALF_N) * 8 + lane]) : 0;
        qa = __ldg(&g_q[n * 32 + lane]);
        qb = __ldg(&g_q[(n + HALF_N) * 32 + lane]);
    }
    while (n < HALF_N) {
        int n2 = n + nw;
        int n2c = (n2 < HALF_N) ? n2 : gw;
        int jva_n = (lane < 8) ? __ldg(&idx[n2c * 8 + lane]) : 0;
        int jvb_n = (lane < 8) ? __ldg(&idx[(n2c + HALF_N) * 8 + lane]) : 0;
        float qa_n = __ldg(&g_q[n2c * 32 + lane]);
        float qb_n = __ldg(&g_q[(n2c + HALF_N) * 32 + lane]);
        int na = n, nb = n + HALF_N;
        int jma = __shfl_sync(FULLM, jva, pair);
        int jmb = __shfl_sync(FULLM, jvb, pair);
        float pda = __ldg(&p[jma * 3 + comp]) - __ldg(&p[na * 3 + comp]);
        float pdb = __ldg(&p[jmb * 3 + comp]) - __ldg(&p[nb * 3 + comp]);
        float a0 = __shfl_sync(FULLM, pda, pair * 3 + 0);
        float a1 = __shfl_sync(FULLM, pda, pair * 3 + 1);
        float a2 = __shfl_sync(FULLM, pda, pair * 3 + 2);
        float b0 = __shfl_sync(FULLM, pdb, pair * 3 + 0);
        float b1 = __shfl_sync(FULLM, pdb, pair * 3 + 1);
        float b2d = __shfl_sync(FULLM, pdb, pair * 3 + 2);
        float ya = wc0 * a0 + wc1 * a1 + wc2 * a2 + b3c;
        float yb = wc0 * b0 + wc1 * b1 + wc2 * b2d + b3c;
        float t3a = fmaxf(0.f, apc * ya + cpc);
        float t3b = fmaxf(0.f, apc * yb + cpc);
#pragma unroll
        for (int ns = 0; ns < 8; ns++) {
            int ja = __shfl_sync(FULLM, jva, ns);
            int jb = __shfl_sync(FULLM, jvb, ns);
            float kva = __ldg(&g_k[ja * 32 + lane]);
            float kvb = __ldg(&g_k[jb * 32 + lane]);
            float at0 = __shfl_sync(FULLM, t3a, ns * 3 + 0);
            float at1 = __shfl_sync(FULLM, t3a, ns * 3 + 1);
            float at2 = __shfl_sync(FULLM, t3a, ns * 3 + 2);
            float bt0 = __shfl_sync(FULLM, t3b, ns * 3 + 0);
            float bt1 = __shfl_sync(FULLM, t3b, ns * 3 + 1);
            float bt2 = __shfl_sync(FULLM, t3b, ns * 3 + 2);
            float prca = w20 * at0 + w21 * at1 + w22 * at2 + b2;
            float prcb = w20 * bt0 + w21 * bt1 + w22 * bt2 + b2;
            float wva = kva - qa + prca;
            float wvb = kvb - qb + prcb;
            s += wva + wvb; ss += wva * wva + wvb * wvb;
        }
        if (lane < 24) {
            g_t3[na * 24 + lane] = t3a;
            g_t3[nb * 24 + lane] = t3b;
        }
        n = n2; jva = jva_n; jvb = jvb_n; qa = qa_n; qb = qb_n;
    }
    atomicAdd(&shs[lane], (double)s);
    atomicAdd(&shq[lane], (double)ss);
    __syncthreads();
    if (tid < 32) {
        atomicAdd(&g_acc[6 + tid], shs[tid]);
        atomicAdd(&g_acc[38 + tid], shq[tid]);
    }
}

// ---------------- K3: t = relu(bn_w(w)) @ Ww1.T + bww1 (warp/2pts, prefetch) -----
__global__ void __launch_bounds__(256, 4) k_t(
        const int* __restrict__ idx,
        const float* __restrict__ Wp2, const float* __restrict__ bp2,
        const float* __restrict__ gw1, const float* __restrict__ bw1,
        const float* __restrict__ Ww1, const float* __restrict__ bww1) {
    __shared__ float s_aw[32], s_cw[32];
    __shared__ __align__(16) float sw[8][2][8][36];
    __shared__ __align__(16) float sWw1[4 * 36];
    __shared__ double sh[8];
    int tid = threadIdx.x, lane = tid & 31, wid = tid >> 5;
    if (tid < 32) {
        double M = (double)NPAIR;
        double m = g_acc[6 + tid] / M;
        double var = g_acc[38 + tid] / M - m * m;
        float a = gw1[tid] * rsqrtf((float)var + EPSBN);
        s_aw[tid] = a; s_cw[tid] = bw1[tid] - (float)m * a;
    }
    if (tid < 128) sWw1[(tid >> 5) * 36 + (tid & 31)] = Ww1[tid];
    if (tid < 8) sh[tid] = 0.0;
    __syncthreads();
    float aw = s_aw[lane], cw = s_cw[lane];
    float w20 = Wp2[lane * 3 + 0], w21 = Wp2[lane * 3 + 1], w22 = Wp2[lane * 3 + 2];
    float b2 = bp2[lane];
    int m4 = lane & 3, pl = lane >> 2;
    float bm = bww1[m4];
    const float4* wr4 = (const float4*)&sWw1[m4 * 36];
    float sm = 0.f, qm = 0.f;
    int gw = blockIdx.x * 8 + wid, nw = gridDim.x * 8;
    int n = gw;
    int jva = 0, jvb = 0; float t3a = 0.f, t3b = 0.f, qa = 0.f, qb = 0.f;
    if (n < HALF_N) {
        jva = (lane < 8) ? __ldg(&idx[n * 8 + lane]) : 0;
        jvb = (lane < 8) ? __ldg(&idx[(n + HALF_N) * 8 + lane]) : 0;
        t3a = (lane < 24) ? __ldg(&g_t3[n * 24 + lane]) : 0.f;
        t3b = (lane < 24) ? __ldg(&g_t3[(n + HALF_N) * 24 + lane]) : 0.f;
        qa = __ldg(&g_q[n * 32 + lane]);
        qb = __ldg(&g_q[(n + HALF_N) * 32 + lane]);
    }
    while (n < HALF_N) {
        int n2 = n + nw;
        int n2c = (n2 < HALF_N) ? n2 : gw;
        int jva_n = (lane < 8) ? __ldg(&idx[n2c * 8 + lane]) : 0;
        int jvb_n = (lane < 8) ? __ldg(&idx[(n2c + HALF_N) * 8 + lane]) : 0;
        float t3a_n = (lane < 24) ? __ldg(&g_t3[n2c * 24 + lane]) : 0.f;
        float t3b_n = (lane < 24) ? __ldg(&g_t3[(n2c + HALF_N) * 24 + lane]) : 0.f;
        float qa_n = __ldg(&g_q[n2c * 32 + lane]);
        float qb_n = __ldg(&g_q[(n2c + HALF_N) * 32 + lane]);
        int na = n, nb = n + HALF_N;
#pragma unroll
        for (int ns = 0; ns < 8; ns++) {
            int ja = __shfl_sync(FULLM, jva, ns);
            int jb = __shfl_sync(FULLM, jvb, ns);
            float kva = __ldg(&g_k[ja * 32 + lane]);
            float kvb = __ldg(&g_k[jb * 32 + lane]);
            float at0 = __shfl_sync(FULLM, t3a, ns * 3 + 0);
            float at1 = __shfl_sync(FULLM, t3a, ns * 3 + 1);
            float at2 = __shfl_sync(FULLM, t3a, ns * 3 + 2);
            float bt0 = __shfl_sync(FULLM, t3b, ns * 3 + 0);
            float bt1 = __shfl_sync(FULLM, t3b, ns * 3 + 1);
            float bt2 = __shfl_sync(FULLM, t3b, ns * 3 + 2);
            float prca = w20 * at0 + w21 * at1 + w22 * at2 + b2;
            float prcb = w20 * bt0 + w21 * bt1 + w22 * bt2 + b2;
            float wva = kva - qa + prca;
            float wvb = kvb - qb + prcb;
            sw[wid][0][ns][lane] = fmaxf(0.f, aw * wva + cw);
            sw[wid][1][ns][lane] = fmaxf(0.f, aw * wvb + cw);
        }
        __syncwarp();
        const float4* a4A = (const float4*)&sw[wid][0][pl][0];
        const float4* a4B = (const float4*)&sw[wid][1][pl][0];
        float ta = bm, tb = bm;
#pragma unroll
        for (int c4 = 0; c4 < 8; c4++) {
            float4 aA = a4A[c4], aB = a4B[c4], b4 = wr4[c4];
            ta += aA.x * b4.x + aA.y * b4.y + aA.z * b4.z + aA.w * b4.w;
            tb += aB.x * b4.x + aB.y * b4.y + aB.z * b4.z + aB.w * b4.w;
        }
        g_t[na * 32 + lane] = ta;
        g_t[nb * 32 + lane] = tb;
        sm += ta + tb; qm += ta * ta + tb * tb;
        __syncwarp();
        n = n2; jva = jva_n; jvb = jvb_n; t3a = t3a_n; t3b = t3b_n; qa = qa_n; qb = qb_n;
    }
#pragma unroll
    for (int o = 4; o < 32; o <<= 1) {
        sm += __shfl_xor_sync(FULLM, sm, o);
        qm += __shfl_xor_sync(FULLM, qm, o);
    }
    if (lane < 4) {
        atomicAdd(&sh[lane], (double)sm);
        atomicAdd(&sh[4 + lane], (double)qm);
    }
    __syncthreads();
    if (tid < 8) atomicAdd(&g_acc[70 + tid], sh[tid]);
}

// ---------------- K4: softmax + weighted sum -> out  (warp/2pts, T-factored) -----
// out[n][c] = sum_ns softw[ns,cg]*v[j_ns][c]  +  Wp2[c]·T[cg] + b2[c]
// where T[cg] = sum_ns softw[ns,cg]*t3[ns][:]   (uses sum softw == 1)
__global__ void __launch_bounds__(256, 5) k_out(
        const int* __restrict__ idx,
        const float* __restrict__ Wp2, const float* __restrict__ bp2,
        const float* __restrict__ gw2, const float* __restrict__ bw2,
        const float* __restrict__ Ww2, const float* __restrict__ bww2,
        float* __restrict__ out) {
    __shared__ float s_at[4], s_ct[4];
    int tid = threadIdx.x, lane = tid & 31, wid = tid >> 5;
    if (tid < 4) {
        double M = (double)NPAIR;
        double m = g_acc[70 + tid] / M;
        double var = g_acc[74 + tid] / M - m * m;
        float a = gw2[tid] * rsqrtf((float)var + EPSBN);
        s_at[tid] = a; s_ct[tid] = bw2[tid] - (float)m * a;
    }
    __syncthreads();
    int m4 = lane & 3, pl = lane >> 2;
    float at0 = s_at[0], at1 = s_at[1], at2 = s_at[2], at3 = s_at[3];
    float ct0 = s_ct[0], ct1 = s_ct[1], ct2 = s_ct[2], ct3 = s_ct[3];
    float v20 = Ww2[m4 * 4 + 0], v21 = Ww2[m4 * 4 + 1];
    float v22 = Ww2[m4 * 4 + 2], v23 = Ww2[m4 * 4 + 3];
    float bcc = bww2[m4];
    float w20 = Wp2[lane * 3 + 0], w21 = Wp2[lane * 3 + 1], w22 = Wp2[lane * 3 + 2];
    float b2 = bp2[lane];
    int gw = blockIdx.x * 8 + wid, nw = gridDim.x * 8;
    for (int n = gw; n < HALF_N; n += nw) {
        int na = n, nb = n + HALF_N;
        int jva = (lane < 8) ? __ldg(&idx[na * 8 + lane]) : 0;
        int jvb = (lane < 8) ? __ldg(&idx[nb * 8 + lane]) : 0;
        float t3a = (lane < 24) ? __ldg(&g_t3[na * 24 + lane]) : 0.f;
        float t3b = (lane < 24) ? __ldg(&g_t3[nb * 24 + lane]) : 0.f;
        float4 t4a = __ldg((const float4*)&g_t[na * 32 + pl * 4]);
        float4 t4b = __ldg((const float4*)&g_t[nb * 32 + pl * 4]);
        // each lane owns logit (pair=pl, cgroup=m4)
        float la, lb;
        {
            float u0 = fmaxf(0.f, at0 * t4a.x + ct0);
            float u1 = fmaxf(0.f, at1 * t4a.y + ct1);
            float u2 = fmaxf(0.f, at2 * t4a.z + ct2);
            float u3 = fmaxf(0.f, at3 * t4a.w + ct3);
            la = v20 * u0 + v21 * u1 + v22 * u2 + v23 * u3 + bcc;
            u0 = fmaxf(0.f, at0 * t4b.x + ct0);
            u1 = fmaxf(0.f, at1 * t4b.y + ct1);
            u2 = fmaxf(0.f, at2 * t4b.z + ct2);
            u3 = fmaxf(0.f, at3 * t4b.w + ct3);
            lb = v20 * u0 + v21 * u1 + v22 * u2 + v23 * u3 + bcc;
        }
        // softmax over pairs (8 lanes sharing m4: xor 4, 8, 16)
        float ma = la, mb = lb;
#pragma unroll
        for (int o = 4; o < 32; o <<= 1) {
            ma = fmaxf(ma, __shfl_xor_sync(FULLM, ma, o));
            mb = fmaxf(mb, __shfl_xor_sync(FULLM, mb, o));
        }
        float ea = __expf(la - ma), eb = __expf(lb - mb);
        float sa = ea, sb = eb;
#pragma unroll
        for (int o = 4; o < 32; o <<= 1) {
            sa += __shfl_xor_sync(FULLM, sa, o);
            sb += __shfl_xor_sync(FULLM, sb, o);
        }
        float wna = ea / sa, wnb = eb / sb;
        // T[cg] = sum_pl softw * t3[pl][:]  -- own-pair t3 then butterfly over pl
        float T0a = wna * __shfl_sync(FULLM, t3a, pl * 3 + 0);
        float T1a = wna * __shfl_sync(FULLM, t3a, pl * 3 + 1);
        float T2a = wna * __shfl_sync(FULLM, t3a, pl * 3 + 2);
        float T0b = wnb * __shfl_sync(FULLM, t3b, pl * 3 + 0);
        float T1b = wnb * __shfl_sync(FULLM, t3b, pl * 3 + 1);
        float T2b = wnb * __shfl_sync(FULLM, t3b, pl * 3 + 2);
#pragma unroll
        for (int o = 4; o < 32; o <<= 1) {
            T0a += __shfl_xor_sync(FULLM, T0a, o);
            T1a += __shfl_xor_sync(FULLM, T1a, o);
            T2a += __shfl_xor_sync(FULLM, T2a, o);
            T0b += __shfl_xor_sync(FULLM, T0b, o);
            T1b += __shfl_xor_sync(FULLM, T1b, o);
            T2b += __shfl_xor_sync(FULLM, T2b, o);
        }
        float pwa = w20 * T0a + w21 * T1a + w22 * T2a + b2;
        float pwb = w20 * T0b + w21 * T1b + w22 * T2b + b2;
        // v accumulation
        float oa = 0.f, ob = 0.f;
#pragma unroll
        for (int ns = 0; ns < 8; ns++) {
            int ja = __shfl_sync(FULLM, jva, ns);
            int jb = __shfl_sync(FULLM, jvb, ns);
            float wga = __shfl_sync(FULLM, wna, ns * 4 + m4);
            float wgb = __shfl_sync(FULLM, wnb, ns * 4 + m4);
            oa += __ldg(&g_v[ja * 32 + lane]) * wga;
            ob += __ldg(&g_v[jb * 32 + lane]) * wgb;
        }
        out[na * 32 + lane] = oa + pwa;
        out[nb * 32 + lane] = ob + pwb;
    }
    // last-finishing block re-zeroes g_acc for the next launch
    __syncthreads();
    if (tid == 0) {
        __threadfence();
        unsigned int tk = atomicAdd(&g_ctr, 1u);
        if (tk == gridDim.x - 1) {
            for (int i = 0; i < 78; i++) g_acc[i] = 0.0;
            g_ctr = 0u;
        }
    }
}

// ---------------- launch ----------------
extern "C" void kernel_launch(void* const* d_in, const int* in_sizes, int n_in,
                              void* d_out, int out_size) {
    const float* p   = (const float*)d_in[0];
    const float* x   = (const float*)d_in[1];
    const int*   idx = (const int*)d_in[2];
    const float* Wq  = (const float*)d_in[3];  const float* bq   = (const float*)d_in[4];
    const float* Wk  = (const float*)d_in[5];  const float* bk   = (const float*)d_in[6];
    const float* Wv  = (const float*)d_in[7];  const float* bv   = (const float*)d_in[8];
    const float* Wp1 = (const float*)d_in[9];  const float* bp1  = (const float*)d_in[10];
    const float* gp  = (const float*)d_in[11]; const float* bp   = (const float*)d_in[12];
    const float* Wp2 = (const float*)d_in[13]; const float* bp2  = (const float*)d_in[14];
    const float* gw1 = (const float*)d_in[15]; const float* bw1  = (const float*)d_in[16];
    const float* Ww1 = (const float*)d_in[17]; const float* bww1 = (const float*)d_in[18];
    const float* gw2 = (const float*)d_in[19]; const float* bw2  = (const float*)d_in[20];
    const float* Ww2 = (const float*)d_in[21]; const float* bww2 = (const float*)d_in[22];
    float* out = (float*)d_out;

    k_fused1<<<QKVB + 2048, 256>>>(p, x, idx, Wq, bq, Wk, bk, Wv, bv, Wp1, bp1);
    k_wt3<<<GATHER_GRID, 256>>>(p, idx, gp, bp, Wp1, bp1, Wp2, bp2);
    k_t<<<GATHER_GRID, 256>>>(idx, Wp2, bp2, gw1, bw1, Ww1, bww1);
    k_out<<<OUT_GRID, 256>>>(idx, Wp2, bp2, gw2, bw2, Ww2, bww2, out);
}

// round 8
// speedup vs baseline: 3.2773x; 1.0486x over previous
#include <cuda_runtime.h>

#define NPTS 262144
#define NSAMP 8
#define NPAIR (NPTS * NSAMP)
#define HALF_N (NPTS / 2)
#define QTR_N (NPTS / 4)
#define EPSBN 1e-5f
#define FULLM 0xffffffffu
#define QKVB 1024
#define G4 592    // 4 blocks/SM * 148 SMs
#define G5 740    // 5 blocks/SM * 148 SMs

typedef unsigned long long ull;

// ---------------- static device scratch (zero-initialized at module load) --------
__device__ float g_q[NPTS * 32];
__device__ float g_k[NPTS * 32];
__device__ float g_v[NPTS * 32];
__device__ float g_t3[NPAIR * 3];   // relu(bn_p(p_r @ Wp1.T + bp1)) per pair (24 MB)
__device__ float g_t[NPAIR * 4];    // t pre-BN (32 MB)
// [0..2] psum [3..5] psq  [6..37] wsum [38..69] wsq  [70..73] tsum [74..77] tsq
__device__ double g_acc[78];
__device__ unsigned int g_ctr;

// ---------------- f32x2 packed-FMA helpers ----------------
__device__ __forceinline__ void ffma2(ull &acc, ull a, ull b) {
    asm("fma.rn.f32x2 %0, %1, %2, %0;" : "+l"(acc) : "l"(a), "l"(b));
}
__device__ __forceinline__ ull pack2(float x) {
    ull r;
    asm("mov.b64 %0, {%1, %1};" : "=l"(r) : "f"(x));
    return r;
}
__device__ __forceinline__ void unpack2(ull v, float &lo, float &hi) {
    asm("mov.b64 {%0, %1}, %2;" : "=f"(lo), "=f"(hi) : "l"(v));
}

// ---------------- K1: fused qkv (blocks 0..QKVB-1, f32x2) + pstats ---------------
__global__ void __launch_bounds__(256) k_fused1(
        const float* __restrict__ p, const float* __restrict__ x,
        const int* __restrict__ idx,
        const float* __restrict__ Wq, const float* __restrict__ bq,
        const float* __restrict__ Wk, const float* __restrict__ bk,
        const float* __restrict__ Wv, const float* __restrict__ bv,
        const float* __restrict__ Wp1, const float* __restrict__ bp1) {
    int tid = threadIdx.x;
    if (blockIdx.x < QKVB) {
        __shared__ float sW[3][1024];
        __shared__ ull sx2[8][4][32];
        __shared__ float sb[3][32];
        for (int e = tid; e < 1024; e += 256) {
            int c = e >> 5, i = e & 31;
            sW[0][i * 32 + c] = Wq[e];
            sW[1][i * 32 + c] = Wk[e];
            sW[2][i * 32 + c] = Wv[e];
        }
        if (tid < 32) { sb[0][tid] = bq[tid]; sb[1][tid] = bk[tid]; sb[2][tid] = bv[tid]; }
        __syncthreads();
        int wid = tid >> 5, lane = tid & 31;
        ull bias2[3] = { pack2(sb[0][lane]), pack2(sb[1][lane]), pack2(sb[2][lane]) };
        float* sxf = (float*)&sx2[wid][0][0];
        for (int chunk = blockIdx.x; chunk < NPTS / 64; chunk += QKVB) {
            int n0 = chunk * 64 + wid * 8;
#pragma unroll
            for (int pp = 0; pp < 8; pp++) {
                float v = x[(n0 + pp) * 32 + lane];
                sxf[((pp >> 1) * 32 + lane) * 2 + (pp & 1)] = v;
            }
            __syncwarp();
            ull acc[3][4];
#pragma unroll
            for (int m = 0; m < 3; m++)
#pragma unroll
                for (int pr = 0; pr < 4; pr++) acc[m][pr] = bias2[m];
#pragma unroll 4
            for (int i = 0; i < 32; i++) {
                ull w0 = pack2(sW[0][i * 32 + lane]);
                ull w1 = pack2(sW[1][i * 32 + lane]);
                ull w2 = pack2(sW[2][i * 32 + lane]);
#pragma unroll
                for (int pr = 0; pr < 4; pr++) {
                    ull xp = sx2[wid][pr][i];
                    ffma2(acc[0][pr], w0, xp);
                    ffma2(acc[1][pr], w1, xp);
                    ffma2(acc[2][pr], w2, xp);
                }
            }
#pragma unroll
            for (int pr = 0; pr < 4; pr++) {
                float lo, hi;
                unpack2(acc[0][pr], lo, hi);
                g_q[(n0 + 2 * pr) * 32 + lane] = lo;
                g_q[(n0 + 2 * pr + 1) * 32 + lane] = hi;
                unpack2(acc[1][pr], lo, hi);
                g_k[(n0 + 2 * pr) * 32 + lane] = lo;
                g_k[(n0 + 2 * pr + 1) * 32 + lane] = hi;
                unpack2(acc[2][pr], lo, hi);
                g_v[(n0 + 2 * pr) * 32 + lane] = lo;
                g_v[(n0 + 2 * pr + 1) * 32 + lane] = hi;
            }
            __syncwarp();
        }
    } else {
        float W[9], b3[3];
#pragma unroll
        for (int i = 0; i < 9; i++) W[i] = Wp1[i];
#pragma unroll
        for (int i = 0; i < 3; i++) b3[i] = bp1[i];
        float s0 = 0, s1 = 0, s2 = 0, q0 = 0, q1 = 0, q2 = 0;
        int bid = blockIdx.x - QKVB;
        for (int pr = bid * 256 + tid; pr < NPAIR; pr += 2048 * 256) {
            int n = pr >> 3;
            int j = __ldg(&idx[pr]);
            float d0 = __ldg(&p[j * 3 + 0]) - __ldg(&p[n * 3 + 0]);
            float d1 = __ldg(&p[j * 3 + 1]) - __ldg(&p[n * 3 + 1]);
            float d2 = __ldg(&p[j * 3 + 2]) - __ldg(&p[n * 3 + 2]);
            float y0 = W[0] * d0 + W[1] * d1 + W[2] * d2 + b3[0];
            float y1 = W[3] * d0 + W[4] * d1 + W[5] * d2 + b3[1];
            float y2 = W[6] * d0 + W[7] * d1 + W[8] * d2 + b3[2];
            s0 += y0; q0 += y0 * y0;
            s1 += y1; q1 += y1 * y1;
            s2 += y2; q2 += y2 * y2;
        }
#pragma unroll
        for (int o = 16; o; o >>= 1) {
            s0 += __shfl_xor_sync(FULLM, s0, o);
            s1 += __shfl_xor_sync(FULLM, s1, o);
            s2 += __shfl_xor_sync(FULLM, s2, o);
            q0 += __shfl_xor_sync(FULLM, q0, o);
            q1 += __shfl_xor_sync(FULLM, q1, o);
            q2 += __shfl_xor_sync(FULLM, q2, o);
        }
        __shared__ double sh[6];
        if (tid < 6) sh[tid] = 0.0;
        __syncthreads();
        if ((tid & 31) == 0) {
            atomicAdd(&sh[0], (double)s0);
            atomicAdd(&sh[1], (double)s1);
            atomicAdd(&sh[2], (double)s2);
            atomicAdd(&sh[3], (double)q0);
            atomicAdd(&sh[4], (double)q1);
            atomicAdd(&sh[5], (double)q2);
        }
        __syncthreads();
        if (tid < 6) atomicAdd(&g_acc[tid], sh[tid]);
    }
}

// ---------------- K2: fused t3-gen + wstats  (warp per 2 points, occ 5) ----------
__global__ void __launch_bounds__(256, 5) k_wt3(
        const float* __restrict__ p, const int* __restrict__ idx,
        const float* __restrict__ gp, const float* __restrict__ bpv,
        const float* __restrict__ Wp1, const float* __restrict__ bp1,
        const float* __restrict__ Wp2, const float* __restrict__ bp2) {
    __shared__ float s_ap[3], s_cp[3];
    __shared__ double shs[32], shq[32];
    int tid = threadIdx.x, lane = tid & 31, wid = tid >> 5;
    if (tid < 3) {
        double M = (double)NPAIR;
        double m = g_acc[tid] / M;
        double var = g_acc[3 + tid] / M - m * m;
        float a = gp[tid] * rsqrtf((float)var + EPSBN);
        s_ap[tid] = a; s_cp[tid] = bpv[tid] - (float)m * a;
    }
    if (tid < 32) { shs[tid] = 0.0; shq[tid] = 0.0; }
    __syncthreads();
    int pr_i = (lane < 24) ? lane : 23;
    int pair = pr_i / 3, comp = pr_i - pair * 3;
    float wc0 = Wp1[comp * 3 + 0], wc1 = Wp1[comp * 3 + 1], wc2 = Wp1[comp * 3 + 2];
    float b3c = bp1[comp];
    float apc = s_ap[comp], cpc = s_cp[comp];
    float w20 = Wp2[lane * 3 + 0], w21 = Wp2[lane * 3 + 1], w22 = Wp2[lane * 3 + 2];
    float b2 = bp2[lane];
    float s = 0.f, ss = 0.f;
    int gw = blockIdx.x * 8 + wid, nw = gridDim.x * 8;
    for (int n = gw; n < HALF_N; n += nw) {
        int na = n, nb = n + HALF_N;
        int jva = (lane < 8) ? __ldg(&idx[na * 8 + lane]) : 0;
        int jvb = (lane < 8) ? __ldg(&idx[nb * 8 + lane]) : 0;
        float qa = __ldg(&g_q[na * 32 + lane]);
        float qb = __ldg(&g_q[nb * 32 + lane]);
        int jma = __shfl_sync(FULLM, jva, pair);
        int jmb = __shfl_sync(FULLM, jvb, pair);
        float pda = __ldg(&p[jma * 3 + comp]) - __ldg(&p[na * 3 + comp]);
        float pdb = __ldg(&p[jmb * 3 + comp]) - __ldg(&p[nb * 3 + comp]);
        float a0 = __shfl_sync(FULLM, pda, pair * 3 + 0);
        float a1 = __shfl_sync(FULLM, pda, pair * 3 + 1);
        float a2 = __shfl_sync(FULLM, pda, pair * 3 + 2);
        float b0 = __shfl_sync(FULLM, pdb, pair * 3 + 0);
        float b1 = __shfl_sync(FULLM, pdb, pair * 3 + 1);
        float b2d = __shfl_sync(FULLM, pdb, pair * 3 + 2);
        float ya = wc0 * a0 + wc1 * a1 + wc2 * a2 + b3c;
        float yb = wc0 * b0 + wc1 * b1 + wc2 * b2d + b3c;
        float t3a = fmaxf(0.f, apc * ya + cpc);
        float t3b = fmaxf(0.f, apc * yb + cpc);
#pragma unroll
        for (int ns = 0; ns < 8; ns++) {
            int ja = __shfl_sync(FULLM, jva, ns);
            int jb = __shfl_sync(FULLM, jvb, ns);
            float kva = __ldg(&g_k[ja * 32 + lane]);
            float kvb = __ldg(&g_k[jb * 32 + lane]);
            float at0 = __shfl_sync(FULLM, t3a, ns * 3 + 0);
            float at1 = __shfl_sync(FULLM, t3a, ns * 3 + 1);
            float at2 = __shfl_sync(FULLM, t3a, ns * 3 + 2);
            float bt0 = __shfl_sync(FULLM, t3b, ns * 3 + 0);
            float bt1 = __shfl_sync(FULLM, t3b, ns * 3 + 1);
            float bt2 = __shfl_sync(FULLM, t3b, ns * 3 + 2);
            float prca = w20 * at0 + w21 * at1 + w22 * at2 + b2;
            float prcb = w20 * bt0 + w21 * bt1 + w22 * bt2 + b2;
            float wva = kva - qa + prca;
            float wvb = kvb - qb + prcb;
            s += wva + wvb; ss += wva * wva + wvb * wvb;
        }
        if (lane < 24) {
            g_t3[na * 24 + lane] = t3a;
            g_t3[nb * 24 + lane] = t3b;
        }
    }
    atomicAdd(&shs[lane], (double)s);
    atomicAdd(&shq[lane], (double)ss);
    __syncthreads();
    if (tid < 32) {
        atomicAdd(&g_acc[6 + tid], shs[tid]);
        atomicAdd(&g_acc[38 + tid], shq[tid]);
    }
}

// ---------------- K3: t = relu(bn_w(w)) @ Ww1.T + bww1 (warp/2pts, occ 5) --------
__global__ void __launch_bounds__(256, 5) k_t(
        const int* __restrict__ idx,
        const float* __restrict__ Wp2, const float* __restrict__ bp2,
        const float* __restrict__ gw1, const float* __restrict__ bw1,
        const float* __restrict__ Ww1, const float* __restrict__ bww1) {
    __shared__ float s_aw[32], s_cw[32];
    __shared__ __align__(16) float sw[8][2][8][36];
    __shared__ __align__(16) float sWw1[4 * 36];
    __shared__ double sh[8];
    int tid = threadIdx.x, lane = tid & 31, wid = tid >> 5;
    if (tid < 32) {
        double M = (double)NPAIR;
        double m = g_acc[6 + tid] / M;
        double var = g_acc[38 + tid] / M - m * m;
        float a = gw1[tid] * rsqrtf((float)var + EPSBN);
        s_aw[tid] = a; s_cw[tid] = bw1[tid] - (float)m * a;
    }
    if (tid < 128) sWw1[(tid >> 5) * 36 + (tid & 31)] = Ww1[tid];
    if (tid < 8) sh[tid] = 0.0;
    __syncthreads();
    float aw = s_aw[lane], cw = s_cw[lane];
    float w20 = Wp2[lane * 3 + 0], w21 = Wp2[lane * 3 + 1], w22 = Wp2[lane * 3 + 2];
    float b2 = bp2[lane];
    int m4 = lane & 3, pl = lane >> 2;
    float bm = bww1[m4];
    const float4* wr4 = (const float4*)&sWw1[m4 * 36];
    float sm = 0.f, qm = 0.f;
    int gw = blockIdx.x * 8 + wid, nw = gridDim.x * 8;
    for (int n = gw; n < HALF_N; n += nw) {
        int na = n, nb = n + HALF_N;
        int jva = (lane < 8) ? __ldg(&idx[na * 8 + lane]) : 0;
        int jvb = (lane < 8) ? __ldg(&idx[nb * 8 + lane]) : 0;
        float t3a = (lane < 24) ? __ldg(&g_t3[na * 24 + lane]) : 0.f;
        float t3b = (lane < 24) ? __ldg(&g_t3[nb * 24 + lane]) : 0.f;
        float qa = __ldg(&g_q[na * 32 + lane]);
        float qb = __ldg(&g_q[nb * 32 + lane]);
#pragma unroll
        for (int ns = 0; ns < 8; ns++) {
            int ja = __shfl_sync(FULLM, jva, ns);
            int jb = __shfl_sync(FULLM, jvb, ns);
            float kva = __ldg(&g_k[ja * 32 + lane]);
            float kvb = __ldg(&g_k[jb * 32 + lane]);
            float at0 = __shfl_sync(FULLM, t3a, ns * 3 + 0);
            float at1 = __shfl_sync(FULLM, t3a, ns * 3 + 1);
            float at2 = __shfl_sync(FULLM, t3a, ns * 3 + 2);
            float bt0 = __shfl_sync(FULLM, t3b, ns * 3 + 0);
            float bt1 = __shfl_sync(FULLM, t3b, ns * 3 + 1);
            float bt2 = __shfl_sync(FULLM, t3b, ns * 3 + 2);
            float prca = w20 * at0 + w21 * at1 + w22 * at2 + b2;
            float prcb = w20 * bt0 + w21 * bt1 + w22 * bt2 + b2;
            float wva = kva - qa + prca;
            float wvb = kvb - qb + prcb;
            sw[wid][0][ns][lane] = fmaxf(0.f, aw * wva + cw);
            sw[wid][1][ns][lane] = fmaxf(0.f, aw * wvb + cw);
        }
        __syncwarp();
        const float4* a4A = (const float4*)&sw[wid][0][pl][0];
        const float4* a4B = (const float4*)&sw[wid][1][pl][0];
        float ta = bm, tb = bm;
#pragma unroll
        for (int c4 = 0; c4 < 8; c4++) {
            float4 aA = a4A[c4], aB = a4B[c4], b4 = wr4[c4];
            ta += aA.x * b4.x + aA.y * b4.y + aA.z * b4.z + aA.w * b4.w;
            tb += aB.x * b4.x + aB.y * b4.y + aB.z * b4.z + aB.w * b4.w;
        }
        g_t[na * 32 + lane] = ta;
        g_t[nb * 32 + lane] = tb;
        sm += ta + tb; qm += ta * ta + tb * tb;
        __syncwarp();
    }
#pragma unroll
    for (int o = 4; o < 32; o <<= 1) {
        sm += __shfl_xor_sync(FULLM, sm, o);
        qm += __shfl_xor_sync(FULLM, qm, o);
    }
    if (lane < 4) {
        atomicAdd(&sh[lane], (double)sm);
        atomicAdd(&sh[4 + lane], (double)qm);
    }
    __syncthreads();
    if (tid < 8) atomicAdd(&g_acc[70 + tid], sh[tid]);
}

// ---------------- K4: softmax + weighted sum -> out  (warp per 4 points) ---------
__global__ void __launch_bounds__(256, 4) k_out(
        const int* __restrict__ idx,
        const float* __restrict__ Wp2, const float* __restrict__ bp2,
        const float* __restrict__ gw2, const float* __restrict__ bw2,
        const float* __restrict__ Ww2, const float* __restrict__ bww2,
        float* __restrict__ out) {
    __shared__ float s_at[4], s_ct[4];
    int tid = threadIdx.x, lane = tid & 31, wid = tid >> 5;
    if (tid < 4) {
        double M = (double)NPAIR;
        double m = g_acc[70 + tid] / M;
        double var = g_acc[74 + tid] / M - m * m;
        float a = gw2[tid] * rsqrtf((float)var + EPSBN);
        s_at[tid] = a; s_ct[tid] = bw2[tid] - (float)m * a;
    }
    __syncthreads();
    int m4 = lane & 3, pl = lane >> 2;
    float at0 = s_at[0], at1 = s_at[1], at2 = s_at[2], at3 = s_at[3];
    float ct0 = s_ct[0], ct1 = s_ct[1], ct2 = s_ct[2], ct3 = s_ct[3];
    float v20 = Ww2[m4 * 4 + 0], v21 = Ww2[m4 * 4 + 1];
    float v22 = Ww2[m4 * 4 + 2], v23 = Ww2[m4 * 4 + 3];
    float bcc = bww2[m4];
    float w20 = Wp2[lane * 3 + 0], w21 = Wp2[lane * 3 + 1], w22 = Wp2[lane * 3 + 2];
    float b2 = bp2[lane];
    int gw = blockIdx.x * 8 + wid, nw = gridDim.x * 8;
    for (int n = gw; n < QTR_N; n += nw) {
        int jv[4];
        float t3[4], l[4];
#pragma unroll
        for (int s4 = 0; s4 < 4; s4++) {
            int nn = n + s4 * QTR_N;
            jv[s4] = (lane < 8) ? __ldg(&idx[nn * 8 + lane]) : 0;
            t3[s4] = (lane < 24) ? __ldg(&g_t3[nn * 24 + lane]) : 0.f;
            float4 t4 = __ldg((const float4*)&g_t[nn * 32 + pl * 4]);
            float u0 = fmaxf(0.f, at0 * t4.x + ct0);
            float u1 = fmaxf(0.f, at1 * t4.y + ct1);
            float u2 = fmaxf(0.f, at2 * t4.z + ct2);
            float u3 = fmaxf(0.f, at3 * t4.w + ct3);
            l[s4] = v20 * u0 + v21 * u1 + v22 * u2 + v23 * u3 + bcc;
        }
        // softmax over pairs (8 lanes sharing m4: xor 4, 8, 16), 4 streams interleaved
        float mx[4];
#pragma unroll
        for (int s4 = 0; s4 < 4; s4++) mx[s4] = l[s4];
#pragma unroll
        for (int o = 4; o < 32; o <<= 1)
#pragma unroll
            for (int s4 = 0; s4 < 4; s4++)
                mx[s4] = fmaxf(mx[s4], __shfl_xor_sync(FULLM, mx[s4], o));
        float wn[4], sum[4];
#pragma unroll
        for (int s4 = 0; s4 < 4; s4++) { wn[s4] = __expf(l[s4] - mx[s4]); sum[s4] = wn[s4]; }
#pragma unroll
        for (int o = 4; o < 32; o <<= 1)
#pragma unroll
            for (int s4 = 0; s4 < 4; s4++)
                sum[s4] += __shfl_xor_sync(FULLM, sum[s4], o);
#pragma unroll
        for (int s4 = 0; s4 < 4; s4++) wn[s4] /= sum[s4];
        // T[cg] = sum_pl softw * t3[pl][:]
        float T0[4], T1[4], T2[4];
#pragma unroll
        for (int s4 = 0; s4 < 4; s4++) {
            T0[s4] = wn[s4] * __shfl_sync(FULLM, t3[s4], pl * 3 + 0);
            T1[s4] = wn[s4] * __shfl_sync(FULLM, t3[s4], pl * 3 + 1);
            T2[s4] = wn[s4] * __shfl_sync(FULLM, t3[s4], pl * 3 + 2);
        }
#pragma unroll
        for (int o = 4; o < 32; o <<= 1)
#pragma unroll
            for (int s4 = 0; s4 < 4; s4++) {
                T0[s4] += __shfl_xor_sync(FULLM, T0[s4], o);
                T1[s4] += __shfl_xor_sync(FULLM, T1[s4], o);
                T2[s4] += __shfl_xor_sync(FULLM, T2[s4], o);
            }
        // v accumulation, 4 streams interleaved
        float o4[4] = {0.f, 0.f, 0.f, 0.f};
#pragma unroll
        for (int ns = 0; ns < 8; ns++)
#pragma unroll
            for (int s4 = 0; s4 < 4; s4++) {
                int j = __shfl_sync(FULLM, jv[s4], ns);
                float wg = __shfl_sync(FULLM, wn[s4], ns * 4 + m4);
                o4[s4] += __ldg(&g_v[j * 32 + lane]) * wg;
            }
#pragma unroll
        for (int s4 = 0; s4 < 4; s4++)
            out[(n + s4 * QTR_N) * 32 + lane] =
                o4[s4] + w20 * T0[s4] + w21 * T1[s4] + w22 * T2[s4] + b2;
    }
    // last-finishing block re-zeroes g_acc for the next launch
    __syncthreads();
    if (tid == 0) {
        __threadfence();
        unsigned int tk = atomicAdd(&g_ctr, 1u);
        if (tk == gridDim.x - 1) {
            for (int i = 0; i < 78; i++) g_acc[i] = 0.0;
            g_ctr = 0u;
        }
    }
}

// ---------------- launch ----------------
extern "C" void kernel_launch(void* const* d_in, const int* in_sizes, int n_in,
                              void* d_out, int out_size) {
    const float* p   = (const float*)d_in[0];
    const float* x   = (const float*)d_in[1];
    const int*   idx = (const int*)d_in[2];
    const float* Wq  = (const float*)d_in[3];  const float* bq   = (const float*)d_in[4];
    const float* Wk  = (const float*)d_in[5];  const float* bk   = (const float*)d_in[6];
    const float* Wv  = (const float*)d_in[7];  const float* bv   = (const float*)d_in[8];
    const float* Wp1 = (const float*)d_in[9];  const float* bp1  = (const float*)d_in[10];
    const float* gp  = (const float*)d_in[11]; const float* bp   = (const float*)d_in[12];
    const float* Wp2 = (const float*)d_in[13]; const float* bp2  = (const float*)d_in[14];
    const float* gw1 = (const float*)d_in[15]; const float* bw1  = (const float*)d_in[16];
    const float* Ww1 = (const float*)d_in[17]; const float* bww1 = (const float*)d_in[18];
    const float* gw2 = (const float*)d_in[19]; const float* bw2  = (const float*)d_in[20];
    const float* Ww2 = (const float*)d_in[21]; const float* bww2 = (const float*)d_in[22];
    float* out = (float*)d_out;

    k_fused1<<<QKVB + 2048, 256>>>(p, x, idx, Wq, bq, Wk, bk, Wv, bv, Wp1, bp1);
    k_wt3<<<G5, 256>>>(p, idx, gp, bp, Wp1, bp1, Wp2, bp2);
    k_t<<<G5, 256>>>(idx, Wp2, bp2, gw1, bw1, Ww1, bww1);
    k_out<<<G4, 256>>>(idx, Wp2, bp2, gw2, bw2, Ww2, bww2, out);
}

// round 9
// speedup vs baseline: 3.4272x; 1.0457x over previous
#include <cuda_runtime.h>

#define NPTS 262144
#define NSAMP 8
#define NPAIR (NPTS * NSAMP)
#define QTR_N (NPTS / 4)
#define EPSBN 1e-5f
#define FULLM 0xffffffffu
#define QKVB 1024
#define G4 592    // 4 blocks/SM * 148 SMs

typedef unsigned long long ull;

// ---------------- static device scratch (zero-initialized at module load) --------
__device__ float g_q[NPTS * 32];
__device__ float g_k[NPTS * 32];
__device__ float g_v[NPTS * 32];
__device__ float g_t3[NPAIR * 3];   // relu(bn_p(p_r @ Wp1.T + bp1)) per pair (24 MB)
__device__ float g_t[NPAIR * 4];    // t pre-BN (32 MB)
// [0..2] psum [3..5] psq  [6..37] wsum [38..69] wsq  [70..73] tsum [74..77] tsq
__device__ double g_acc[78];
__device__ unsigned int g_ctr;

// ---------------- f32x2 packed-FMA helpers ----------------
__device__ __forceinline__ void ffma2(ull &acc, ull a, ull b) {
    asm("fma.rn.f32x2 %0, %1, %2, %0;" : "+l"(acc) : "l"(a), "l"(b));
}
__device__ __forceinline__ ull pack2(float x) {
    ull r;
    asm("mov.b64 %0, {%1, %1};" : "=l"(r) : "f"(x));
    return r;
}
__device__ __forceinline__ void unpack2(ull v, float &lo, float &hi) {
    asm("mov.b64 {%0, %1}, %2;" : "=f"(lo), "=f"(hi) : "l"(v));
}

// ---------------- K1: fused qkv (blocks 0..QKVB-1, f32x2) + pstats ---------------
__global__ void __launch_bounds__(256) k_fused1(
        const float* __restrict__ p, const float* __restrict__ x,
        const int* __restrict__ idx,
        const float* __restrict__ Wq, const float* __restrict__ bq,
        const float* __restrict__ Wk, const float* __restrict__ bk,
        const float* __restrict__ Wv, const float* __restrict__ bv,
        const float* __restrict__ Wp1, const float* __restrict__ bp1) {
    int tid = threadIdx.x;
    if (blockIdx.x < QKVB) {
        __shared__ float sW[3][1024];
        __shared__ ull sx2[8][4][32];
        __shared__ float sb[3][32];
        for (int e = tid; e < 1024; e += 256) {
            int c = e >> 5, i = e & 31;
            sW[0][i * 32 + c] = Wq[e];
            sW[1][i * 32 + c] = Wk[e];
            sW[2][i * 32 + c] = Wv[e];
        }
        if (tid < 32) { sb[0][tid] = bq[tid]; sb[1][tid] = bk[tid]; sb[2][tid] = bv[tid]; }
        __syncthreads();
        int wid = tid >> 5, lane = tid & 31;
        ull bias2[3] = { pack2(sb[0][lane]), pack2(sb[1][lane]), pack2(sb[2][lane]) };
        float* sxf = (float*)&sx2[wid][0][0];
        for (int chunk = blockIdx.x; chunk < NPTS / 64; chunk += QKVB) {
            int n0 = chunk * 64 + wid * 8;
#pragma unroll
            for (int pp = 0; pp < 8; pp++) {
                float v = x[(n0 + pp) * 32 + lane];
                sxf[((pp >> 1) * 32 + lane) * 2 + (pp & 1)] = v;
            }
            __syncwarp();
            ull acc[3][4];
#pragma unroll
            for (int m = 0; m < 3; m++)
#pragma unroll
                for (int pr = 0; pr < 4; pr++) acc[m][pr] = bias2[m];
#pragma unroll 4
            for (int i = 0; i < 32; i++) {
                ull w0 = pack2(sW[0][i * 32 + lane]);
                ull w1 = pack2(sW[1][i * 32 + lane]);
                ull w2 = pack2(sW[2][i * 32 + lane]);
#pragma unroll
                for (int pr = 0; pr < 4; pr++) {
                    ull xp = sx2[wid][pr][i];
                    ffma2(acc[0][pr], w0, xp);
                    ffma2(acc[1][pr], w1, xp);
                    ffma2(acc[2][pr], w2, xp);
                }
            }
#pragma unroll
            for (int pr = 0; pr < 4; pr++) {
                float lo, hi;
                unpack2(acc[0][pr], lo, hi);
                g_q[(n0 + 2 * pr) * 32 + lane] = lo;
                g_q[(n0 + 2 * pr + 1) * 32 + lane] = hi;
                unpack2(acc[1][pr], lo, hi);
                g_k[(n0 + 2 * pr) * 32 + lane] = lo;
                g_k[(n0 + 2 * pr + 1) * 32 + lane] = hi;
                unpack2(acc[2][pr], lo, hi);
                g_v[(n0 + 2 * pr) * 32 + lane] = lo;
                g_v[(n0 + 2 * pr + 1) * 32 + lane] = hi;
            }
            __syncwarp();
        }
    } else {
        float W[9], b3[3];
#pragma unroll
        for (int i = 0; i < 9; i++) W[i] = Wp1[i];
#pragma unroll
        for (int i = 0; i < 3; i++) b3[i] = bp1[i];
        float s0 = 0, s1 = 0, s2 = 0, q0 = 0, q1 = 0, q2 = 0;
        int bid = blockIdx.x - QKVB;
        for (int pr = bid * 256 + tid; pr < NPAIR; pr += 2048 * 256) {
            int n = pr >> 3;
            int j = __ldg(&idx[pr]);
            float d0 = __ldg(&p[j * 3 + 0]) - __ldg(&p[n * 3 + 0]);
            float d1 = __ldg(&p[j * 3 + 1]) - __ldg(&p[n * 3 + 1]);
            float d2 = __ldg(&p[j * 3 + 2]) - __ldg(&p[n * 3 + 2]);
            float y0 = W[0] * d0 + W[1] * d1 + W[2] * d2 + b3[0];
            float y1 = W[3] * d0 + W[4] * d1 + W[5] * d2 + b3[1];
            float y2 = W[6] * d0 + W[7] * d1 + W[8] * d2 + b3[2];
            s0 += y0; q0 += y0 * y0;
            s1 += y1; q1 += y1 * y1;
            s2 += y2; q2 += y2 * y2;
        }
#pragma unroll
        for (int o = 16; o; o >>= 1) {
            s0 += __shfl_xor_sync(FULLM, s0, o);
            s1 += __shfl_xor_sync(FULLM, s1, o);
            s2 += __shfl_xor_sync(FULLM, s2, o);
            q0 += __shfl_xor_sync(FULLM, q0, o);
            q1 += __shfl_xor_sync(FULLM, q1, o);
            q2 += __shfl_xor_sync(FULLM, q2, o);
        }
        __shared__ double sh[6];
        if (tid < 6) sh[tid] = 0.0;
        __syncthreads();
        if ((tid & 31) == 0) {
            atomicAdd(&sh[0], (double)s0);
            atomicAdd(&sh[1], (double)s1);
            atomicAdd(&sh[2], (double)s2);
            atomicAdd(&sh[3], (double)q0);
            atomicAdd(&sh[4], (double)q1);
            atomicAdd(&sh[5], (double)q2);
        }
        __syncthreads();
        if (tid < 6) atomicAdd(&g_acc[tid], sh[tid]);
    }
}

// ---------------- K2: fused t3-gen + wstats  (warp per 4 points) -----------------
__global__ void __launch_bounds__(256, 4) k_wt3(
        const float* __restrict__ p, const int* __restrict__ idx,
        const float* __restrict__ gp, const float* __restrict__ bpv,
        const float* __restrict__ Wp1, const float* __restrict__ bp1,
        const float* __restrict__ Wp2, const float* __restrict__ bp2) {
    __shared__ float s_ap[3], s_cp[3];
    __shared__ double shs[32], shq[32];
    int tid = threadIdx.x, lane = tid & 31, wid = tid >> 5;
    if (tid < 3) {
        double M = (double)NPAIR;
        double m = g_acc[tid] / M;
        double var = g_acc[3 + tid] / M - m * m;
        float a = gp[tid] * rsqrtf((float)var + EPSBN);
        s_ap[tid] = a; s_cp[tid] = bpv[tid] - (float)m * a;
    }
    if (tid < 32) { shs[tid] = 0.0; shq[tid] = 0.0; }
    __syncthreads();
    int pr_i = (lane < 24) ? lane : 23;
    int pair = pr_i / 3, comp = pr_i - pair * 3;
    float wc0 = Wp1[comp * 3 + 0], wc1 = Wp1[comp * 3 + 1], wc2 = Wp1[comp * 3 + 2];
    float b3c = bp1[comp];
    float apc = s_ap[comp], cpc = s_cp[comp];
    float w20 = Wp2[lane * 3 + 0], w21 = Wp2[lane * 3 + 1], w22 = Wp2[lane * 3 + 2];
    float b2 = bp2[lane];
    float s = 0.f, ss = 0.f;
    int gw = blockIdx.x * 8 + wid, nw = gridDim.x * 8;
    for (int n = gw; n < QTR_N; n += nw) {
        int jv[4];
        float qv[4], t3[4];
#pragma unroll
        for (int s4 = 0; s4 < 4; s4++) {
            int nn = n + s4 * QTR_N;
            jv[s4] = (lane < 8) ? __ldg(&idx[nn * 8 + lane]) : 0;
            qv[s4] = __ldg(&g_q[nn * 32 + lane]);
        }
        // t3 generation, 4 streams interleaved
        float pd[4];
#pragma unroll
        for (int s4 = 0; s4 < 4; s4++) {
            int nn = n + s4 * QTR_N;
            int jm = __shfl_sync(FULLM, jv[s4], pair);
            pd[s4] = __ldg(&p[jm * 3 + comp]) - __ldg(&p[nn * 3 + comp]);
        }
#pragma unroll
        for (int s4 = 0; s4 < 4; s4++) {
            float d0 = __shfl_sync(FULLM, pd[s4], pair * 3 + 0);
            float d1 = __shfl_sync(FULLM, pd[s4], pair * 3 + 1);
            float d2 = __shfl_sync(FULLM, pd[s4], pair * 3 + 2);
            float y = wc0 * d0 + wc1 * d1 + wc2 * d2 + b3c;
            t3[s4] = fmaxf(0.f, apc * y + cpc);
        }
#pragma unroll
        for (int ns = 0; ns < 8; ns++)
#pragma unroll
            for (int s4 = 0; s4 < 4; s4++) {
                int j = __shfl_sync(FULLM, jv[s4], ns);
                float kv = __ldg(&g_k[j * 32 + lane]);
                float t0 = __shfl_sync(FULLM, t3[s4], ns * 3 + 0);
                float t1 = __shfl_sync(FULLM, t3[s4], ns * 3 + 1);
                float t2 = __shfl_sync(FULLM, t3[s4], ns * 3 + 2);
                float prc = w20 * t0 + w21 * t1 + w22 * t2 + b2;
                float wv = kv - qv[s4] + prc;
                s += wv; ss += wv * wv;
            }
        if (lane < 24) {
#pragma unroll
            for (int s4 = 0; s4 < 4; s4++)
                g_t3[(n + s4 * QTR_N) * 24 + lane] = t3[s4];
        }
    }
    atomicAdd(&shs[lane], (double)s);
    atomicAdd(&shq[lane], (double)ss);
    __syncthreads();
    if (tid < 32) {
        atomicAdd(&g_acc[6 + tid], shs[tid]);
        atomicAdd(&g_acc[38 + tid], shq[tid]);
    }
}

// ---------------- K3: t = relu(bn_w(w)) @ Ww1.T + bww1  (warp per 4 points) ------
__global__ void __launch_bounds__(256, 4) k_t(
        const int* __restrict__ idx,
        const float* __restrict__ Wp2, const float* __restrict__ bp2,
        const float* __restrict__ gw1, const float* __restrict__ bw1,
        const float* __restrict__ Ww1, const float* __restrict__ bww1) {
    __shared__ float s_aw[32], s_cw[32];
    __shared__ __align__(16) float sw[8][4][8][36];
    __shared__ __align__(16) float sWw1[4 * 36];
    __shared__ double sh[8];
    int tid = threadIdx.x, lane = tid & 31, wid = tid >> 5;
    if (tid < 32) {
        double M = (double)NPAIR;
        double m = g_acc[6 + tid] / M;
        double var = g_acc[38 + tid] / M - m * m;
        float a = gw1[tid] * rsqrtf((float)var + EPSBN);
        s_aw[tid] = a; s_cw[tid] = bw1[tid] - (float)m * a;
    }
    if (tid < 128) sWw1[(tid >> 5) * 36 + (tid & 31)] = Ww1[tid];
    if (tid < 8) sh[tid] = 0.0;
    __syncthreads();
    float aw = s_aw[lane], cw = s_cw[lane];
    float w20 = Wp2[lane * 3 + 0], w21 = Wp2[lane * 3 + 1], w22 = Wp2[lane * 3 + 2];
    float b2 = bp2[lane];
    int m4 = lane & 3, pl = lane >> 2;
    float bm = bww1[m4];
    const float4* wr4 = (const float4*)&sWw1[m4 * 36];
    float sm = 0.f, qm = 0.f;
    int gw = blockIdx.x * 8 + wid, nw = gridDim.x * 8;
    for (int n = gw; n < QTR_N; n += nw) {
        int jv[4];
        float qv[4], t3[4];
#pragma unroll
        for (int s4 = 0; s4 < 4; s4++) {
            int nn = n + s4 * QTR_N;
            jv[s4] = (lane < 8) ? __ldg(&idx[nn * 8 + lane]) : 0;
            t3[s4] = (lane < 24) ? __ldg(&g_t3[nn * 24 + lane]) : 0.f;
            qv[s4] = __ldg(&g_q[nn * 32 + lane]);
        }
#pragma unroll
        for (int ns = 0; ns < 8; ns++)
#pragma unroll
            for (int s4 = 0; s4 < 4; s4++) {
                int j = __shfl_sync(FULLM, jv[s4], ns);
                float kv = __ldg(&g_k[j * 32 + lane]);
                float t0 = __shfl_sync(FULLM, t3[s4], ns * 3 + 0);
                float t1 = __shfl_sync(FULLM, t3[s4], ns * 3 + 1);
                float t2 = __shfl_sync(FULLM, t3[s4], ns * 3 + 2);
                float prc = w20 * t0 + w21 * t1 + w22 * t2 + b2;
                float wv = kv - qv[s4] + prc;
                sw[wid][s4][ns][lane] = fmaxf(0.f, aw * wv + cw);
            }
        __syncwarp();
        float tv[4] = {bm, bm, bm, bm};
#pragma unroll
        for (int c4 = 0; c4 < 8; c4++) {
            float4 b4 = wr4[c4];
#pragma unroll
            for (int s4 = 0; s4 < 4; s4++) {
                float4 a4 = ((const float4*)&sw[wid][s4][pl][0])[c4];
                tv[s4] += a4.x * b4.x + a4.y * b4.y + a4.z * b4.z + a4.w * b4.w;
            }
        }
#pragma unroll
        for (int s4 = 0; s4 < 4; s4++) {
            g_t[(n + s4 * QTR_N) * 32 + lane] = tv[s4];
            sm += tv[s4]; qm += tv[s4] * tv[s4];
        }
        __syncwarp();
    }
#pragma unroll
    for (int o = 4; o < 32; o <<= 1) {
        sm += __shfl_xor_sync(FULLM, sm, o);
        qm += __shfl_xor_sync(FULLM, qm, o);
    }
    if (lane < 4) {
        atomicAdd(&sh[lane], (double)sm);
        atomicAdd(&sh[4 + lane], (double)qm);
    }
    __syncthreads();
    if (tid < 8) atomicAdd(&g_acc[70 + tid], sh[tid]);
}

// ---------------- K4: softmax + weighted sum -> out  (warp per 4 points) ---------
__global__ void __launch_bounds__(256, 4) k_out(
        const int* __restrict__ idx,
        const float* __restrict__ Wp2, const float* __restrict__ bp2,
        const float* __restrict__ gw2, const float* __restrict__ bw2,
        const float* __restrict__ Ww2, const float* __restrict__ bww2,
        float* __restrict__ out) {
    __shared__ float s_at[4], s_ct[4];
    int tid = threadIdx.x, lane = tid & 31, wid = tid >> 5;
    if (tid < 4) {
        double M = (double)NPAIR;
        double m = g_acc[70 + tid] / M;
        double var = g_acc[74 + tid] / M - m * m;
        float a = gw2[tid] * rsqrtf((float)var + EPSBN);
        s_at[tid] = a; s_ct[tid] = bw2[tid] - (float)m * a;
    }
    __syncthreads();
    int m4 = lane & 3, pl = lane >> 2;
    float at0 = s_at[0], at1 = s_at[1], at2 = s_at[2], at3 = s_at[3];
    float ct0 = s_ct[0], ct1 = s_ct[1], ct2 = s_ct[2], ct3 = s_ct[3];
    float v20 = Ww2[m4 * 4 + 0], v21 = Ww2[m4 * 4 + 1];
    float v22 = Ww2[m4 * 4 + 2], v23 = Ww2[m4 * 4 + 3];
    float bcc = bww2[m4];
    float w20 = Wp2[lane * 3 + 0], w21 = Wp2[lane * 3 + 1], w22 = Wp2[lane * 3 + 2];
    float b2 = bp2[lane];
    int gw = blockIdx.x * 8 + wid, nw = gridDim.x * 8;
    for (int n = gw; n < QTR_N; n += nw) {
        int jv[4];
        float t3[4], l[4];
#pragma unroll
        for (int s4 = 0; s4 < 4; s4++) {
            int nn = n + s4 * QTR_N;
            jv[s4] = (lane < 8) ? __ldg(&idx[nn * 8 + lane]) : 0;
            t3[s4] = (lane < 24) ? __ldg(&g_t3[nn * 24 + lane]) : 0.f;
            float4 t4 = __ldg((const float4*)&g_t[nn * 32 + pl * 4]);
            float u0 = fmaxf(0.f, at0 * t4.x + ct0);
            float u1 = fmaxf(0.f, at1 * t4.y + ct1);
            float u2 = fmaxf(0.f, at2 * t4.z + ct2);
            float u3 = fmaxf(0.f, at3 * t4.w + ct3);
            l[s4] = v20 * u0 + v21 * u1 + v22 * u2 + v23 * u3 + bcc;
        }
        float mx[4];
#pragma unroll
        for (int s4 = 0; s4 < 4; s4++) mx[s4] = l[s4];
#pragma unroll
        for (int o = 4; o < 32; o <<= 1)
#pragma unroll
            for (int s4 = 0; s4 < 4; s4++)
                mx[s4] = fmaxf(mx[s4], __shfl_xor_sync(FULLM, mx[s4], o));
        float wn[4], sum[4];
#pragma unroll
        for (int s4 = 0; s4 < 4; s4++) { wn[s4] = __expf(l[s4] - mx[s4]); sum[s4] = wn[s4]; }
#pragma unroll
        for (int o = 4; o < 32; o <<= 1)
#pragma unroll
            for (int s4 = 0; s4 < 4; s4++)
                sum[s4] += __shfl_xor_sync(FULLM, sum[s4], o);
#pragma unroll
        for (int s4 = 0; s4 < 4; s4++) wn[s4] /= sum[s4];
        float T0[4], T1[4], T2[4];
#pragma unroll
        for (int s4 = 0; s4 < 4; s4++) {
            T0[s4] = wn[s4] * __shfl_sync(FULLM, t3[s4], pl * 3 + 0);
            T1[s4] = wn[s4] * __shfl_sync(FULLM, t3[s4], pl * 3 + 1);
            T2[s4] = wn[s4] * __shfl_sync(FULLM, t3[s4], pl * 3 + 2);
        }
#pragma unroll
        for (int o = 4; o < 32; o <<= 1)
#pragma unroll
            for (int s4 = 0; s4 < 4; s4++) {
                T0[s4] += __shfl_xor_sync(FULLM, T0[s4], o);
                T1[s4] += __shfl_xor_sync(FULLM, T1[s4], o);
                T2[s4] += __shfl_xor_sync(FULLM, T2[s4], o);
            }
        float o4[4] = {0.f, 0.f, 0.f, 0.f};
#pragma unroll
        for (int ns = 0; ns < 8; ns++)
#pragma unroll
            for (int s4 = 0; s4 < 4; s4++) {
                int j = __shfl_sync(FULLM, jv[s4], ns);
                float wg = __shfl_sync(FULLM, wn[s4], ns * 4 + m4);
                o4[s4] += __ldg(&g_v[j * 32 + lane]) * wg;
            }
#pragma unroll
        for (int s4 = 0; s4 < 4; s4++)
            out[(n + s4 * QTR_N) * 32 + lane] =
                o4[s4] + w20 * T0[s4] + w21 * T1[s4] + w22 * T2[s4] + b2;
    }
    __syncthreads();
    if (tid == 0) {
        __threadfence();
        unsigned int tk = atomicAdd(&g_ctr, 1u);
        if (tk == gridDim.x - 1) {
            for (int i = 0; i < 78; i++) g_acc[i] = 0.0;
            g_ctr = 0u;
        }
    }
}

// ---------------- launch ----------------
extern "C" void kernel_launch(void* const* d_in, const int* in_sizes, int n_in,
                              void* d_out, int out_size) {
    const float* p   = (const float*)d_in[0];
    const float* x   = (const float*)d_in[1];
    const int*   idx = (const int*)d_in[2];
    const float* Wq  = (const float*)d_in[3];  const float* bq   = (const float*)d_in[4];
    const float* Wk  = (const float*)d_in[5];  const float* bk   = (const float*)d_in[6];
    const float* Wv  = (const float*)d_in[7];  const float* bv   = (const float*)d_in[8];
    const float* Wp1 = (const float*)d_in[9];  const float* bp1  = (const float*)d_in[10];
    const float* gp  = (const float*)d_in[11]; const float* bp   = (const float*)d_in[12];
    const float* Wp2 = (const float*)d_in[13]; const float* bp2  = (const float*)d_in[14];
    const float* gw1 = (const float*)d_in[15]; const float* bw1  = (const float*)d_in[16];
    const float* Ww1 = (const float*)d_in[17]; const float* bww1 = (const float*)d_in[18];
    const float* gw2 = (const float*)d_in[19]; const float* bw2  = (const float*)d_in[20];
    const float* Ww2 = (const float*)d_in[21]; const float* bww2 = (const float*)d_in[22];
    float* out = (float*)d_out;

    k_fused1<<<QKVB + 2048, 256>>>(p, x, idx, Wq, bq, Wk, bk, Wv, bv, Wp1, bp1);
    k_wt3<<<G4, 256>>>(p, idx, gp, bp, Wp1, bp1, Wp2, bp2);
    k_t<<<G4, 256>>>(idx, Wp2, bp2, gw1, bw1, Ww1, bww1);
    k_out<<<G4, 256>>>(idx, Wp2, bp2, gw2, bw2, Ww2, bww2, out);
}